// round 12
// baseline (speedup 1.0000x reference)
#include <cuda_runtime.h>
#include <cuda_fp16.h>
#include <math.h>

// ---------------- problem constants ----------------------------------------
#define NB   2
#define LQ   5440
#define CC   256
#define HH   4
#define LL   4
#define PP   8
#define HD   64
#define LIN  5440
#define NQ   (NB * LQ)   // 10880
#define NKV  (NB * LIN)  // 10880
#define HLP  128
#define HLP2 256
#define NOA  384

// ---------------- scratch ---------------------------------------------------
__device__ __half g_q_h[NQ * CC];
__device__ __half g_key_h[NKV * CC];
__device__ __half g_value_h[NKV * CC];
__device__ __half g_oa_h[NQ * NOA];
__device__ __half g_Wv_h[CC * CC];
__device__ __half g_Woa_h[CC * NOA];
__device__ __half g_Wo_h[CC * CC];
__device__ float  g_boa[NOA];
__device__ __half g_sampled_h[NQ * CC];

// ---------------- single prep kernel ----------------------------------------
#define N8 (NQ * CC / 8)
#define WPREP (CC * NOA)
__global__ __launch_bounds__(256)
void prep_kernel(const float* __restrict__ src,
                 const float* __restrict__ pos,
                 const float* __restrict__ key,
                 const float* __restrict__ Wv,
                 const float* __restrict__ Woff,
                 const float* __restrict__ Wattn,
                 const float* __restrict__ boff,
                 const float* __restrict__ battn,
                 const float* __restrict__ Wo,
                 __half* __restrict__ qh,
                 __half* __restrict__ keyh,
                 __half* __restrict__ Wvh,
                 __half* __restrict__ Woah,
                 __half* __restrict__ Woh,
                 float* __restrict__ boa) {
    int i = blockIdx.x * blockDim.x + threadIdx.x;
    if (i < N8) {
        float4 s0 = ((const float4*)src)[i * 2];
        float4 s1 = ((const float4*)src)[i * 2 + 1];
        float4 p0 = ((const float4*)pos)[i * 2];
        float4 p1 = ((const float4*)pos)[i * 2 + 1];
        __half2 h0 = __floats2half2_rn(s0.x + p0.x, s0.y + p0.y);
        __half2 h1 = __floats2half2_rn(s0.z + p0.z, s0.w + p0.w);
        __half2 h2 = __floats2half2_rn(s1.x + p1.x, s1.y + p1.y);
        __half2 h3 = __floats2half2_rn(s1.z + p1.z, s1.w + p1.w);
        uint4 o; o.x = *(unsigned*)&h0; o.y = *(unsigned*)&h1;
        o.z = *(unsigned*)&h2; o.w = *(unsigned*)&h3;
        ((uint4*)qh)[i] = o;
    } else if (i < 2 * N8) {
        int j = i - N8;
        float4 k0 = ((const float4*)key)[j * 2];
        float4 k1 = ((const float4*)key)[j * 2 + 1];
        __half2 h0 = __floats2half2_rn(k0.x, k0.y);
        __half2 h1 = __floats2half2_rn(k0.z, k0.w);
        __half2 h2 = __floats2half2_rn(k1.x, k1.y);
        __half2 h3 = __floats2half2_rn(k1.z, k1.w);
        uint4 o; o.x = *(unsigned*)&h0; o.y = *(unsigned*)&h1;
        o.z = *(unsigned*)&h2; o.w = *(unsigned*)&h3;
        ((uint4*)keyh)[j] = o;
    } else {
        int j = i - 2 * N8;
        if (j < WPREP) {
            if (j < CC * CC) {
                Wvh[j] = __float2half(Wv[j]);
                Woh[j] = __float2half(Wo[j]);
            }
            int k = j / NOA, n = j % NOA;
            float w = (n < HLP2) ? Woff[k * HLP2 + n] : Wattn[k * HLP + (n - HLP2)];
            Woah[j] = __float2half(w);
            if (j < NOA) boa[j] = (j < HLP2) ? boff[j] : battn[j - HLP2];
        }
    }
}

// ---------------- GEMM primitives -------------------------------------------
#define GBK 32
#define KITERS 8
#define AS_STRIDE 40

__device__ __forceinline__ void cp16(unsigned dst, const void* src) {
    asm volatile("cp.async.cg.shared.global [%0], [%1], 16;\n" :: "r"(dst), "l"(src));
}
__device__ __forceinline__ void cp_commit() {
    asm volatile("cp.async.commit_group;\n");
}
template <int N>
__device__ __forceinline__ void cp_wait() {
    asm volatile("cp.async.wait_group %0;\n" :: "n"(N));
}
__device__ __forceinline__ void ldm_x4(unsigned& r0, unsigned& r1,
                                       unsigned& r2, unsigned& r3, unsigned addr) {
    asm volatile("ldmatrix.sync.aligned.m8n8.x4.shared.b16 {%0,%1,%2,%3}, [%4];"
                 : "=r"(r0), "=r"(r1), "=r"(r2), "=r"(r3) : "r"(addr));
}
__device__ __forceinline__ void ldm_x4_t(unsigned& r0, unsigned& r1,
                                         unsigned& r2, unsigned& r3, unsigned addr) {
    asm volatile("ldmatrix.sync.aligned.m8n8.x4.trans.shared.b16 {%0,%1,%2,%3}, [%4];"
                 : "=r"(r0), "=r"(r1), "=r"(r2), "=r"(r3) : "r"(addr));
}
__device__ __forceinline__ void mma16816(float& c0, float& c1, float& c2, float& c3,
                                         unsigned a0, unsigned a1, unsigned a2, unsigned a3,
                                         unsigned b0, unsigned b1) {
    asm volatile(
        "mma.sync.aligned.m16n8k16.row.col.f32.f16.f16.f32 "
        "{%0,%1,%2,%3}, {%4,%5,%6,%7}, {%8,%9}, {%0,%1,%2,%3};"
        : "+f"(c0), "+f"(c1), "+f"(c2), "+f"(c3)
        : "r"(a0), "r"(a1), "r"(a2), "r"(a3), "r"(b0), "r"(b1));
}

// ---- front GEMM: BM=64, BN=128, 128 thr, 4-stage cp.async (dynamic smem) ---
#define FB_STRIDE 136
struct FrontSmem {
    __half As[4][64][AS_STRIDE];   // 20480 B
    __half Bs[4][GBK][FB_STRIDE];  // 34816 B -> 55296 total
};
#define FRONT_SMEM_BYTES 55296

__global__ __launch_bounds__(128)
void hgemm_front(const __half* __restrict__ keyh, const __half* __restrict__ Wvh,
                 const float* __restrict__ bval,  __half* __restrict__ valueh,
                 const __half* __restrict__ qh,   const __half* __restrict__ Woah,
                 const float* __restrict__ boa,   __half* __restrict__ oa) {
    extern __shared__ char smem_raw[];
    FrontSmem& sm = *(FrontSmem*)smem_raw;
    const int tid  = threadIdx.x;
    const int lane = tid & 31;
    const int warp = tid >> 5;
    const int wm = warp >> 1;
    const int wn = warp & 1;

    const int job  = (blockIdx.y < 2) ? 0 : 1;
    const int coly = job ? (blockIdx.y - 2) : blockIdx.y;
    const int N    = job ? NOA : CC;
    const __half* A = job ? qh : keyh;
    const __half* B = job ? Woah : Wvh;
    const float* bias = job ? boa : bval;

    const int row0 = blockIdx.x * 64;
    const int col0 = coly * 128;

    const int a_r = tid >> 2;
    const int a_c = (tid & 3) << 3;
    const int b_r = tid >> 4;
    const int b_c = (tid & 15) << 3;

    const __half* Aptr = A + (size_t)row0 * 256;
    const __half* Bptr = B + col0;

    auto issue_stage = [&](int s, int k0) {
        cp16((unsigned)__cvta_generic_to_shared(&sm.As[s][a_r][a_c]),
             Aptr + (size_t)a_r * 256 + k0 + a_c);
        cp16((unsigned)__cvta_generic_to_shared(&sm.As[s][a_r + 32][a_c]),
             Aptr + (size_t)(a_r + 32) * 256 + k0 + a_c);
        #pragma unroll
        for (int rr = 0; rr < 4; rr++)
            cp16((unsigned)__cvta_generic_to_shared(&sm.Bs[s][b_r + rr * 8][b_c]),
                 Bptr + (size_t)(k0 + b_r + rr * 8) * N + b_c);
    };

    issue_stage(0, 0);       cp_commit();
    issue_stage(1, GBK);     cp_commit();
    issue_stage(2, 2 * GBK); cp_commit();

    float acc[2][8][4] = {};
    const int a_lrow = lane & 15;
    const int a_lcol = (lane >> 4) << 3;

    #pragma unroll 1
    for (int t = 0; t < KITERS; t++) {
        const int sb = t & 3;
        cp_wait<2>();
        __syncthreads();

        if (t + 3 < KITERS) issue_stage((t + 3) & 3, (t + 3) * GBK);
        cp_commit();

        #pragma unroll
        for (int ks = 0; ks < 2; ks++) {
            const int kk = ks * 16;
            unsigned af[2][4], bf[8][2];
            #pragma unroll
            for (int mt = 0; mt < 2; mt++) {
                unsigned addr = (unsigned)__cvta_generic_to_shared(
                    &sm.As[sb][wm * 32 + mt * 16 + a_lrow][kk + a_lcol]);
                ldm_x4(af[mt][0], af[mt][1], af[mt][2], af[mt][3], addr);
            }
            #pragma unroll
            for (int nt = 0; nt < 4; nt++) {
                unsigned addr = (unsigned)__cvta_generic_to_shared(
                    &sm.Bs[sb][kk + a_lrow][wn * 64 + nt * 16 + a_lcol]);
                unsigned r0, r1, r2, r3;
                ldm_x4_t(r0, r1, r2, r3, addr);
                bf[nt * 2 + 0][0] = r0; bf[nt * 2 + 0][1] = r1;
                bf[nt * 2 + 1][0] = r2; bf[nt * 2 + 1][1] = r3;
            }
            #pragma unroll
            for (int mt = 0; mt < 2; mt++)
                #pragma unroll
                for (int j = 0; j < 8; j++)
                    mma16816(acc[mt][j][0], acc[mt][j][1], acc[mt][j][2], acc[mt][j][3],
                             af[mt][0], af[mt][1], af[mt][2], af[mt][3],
                             bf[j][0], bf[j][1]);
        }
    }

    const int g  = lane >> 2;
    const int tq = (lane & 3) << 1;
    #pragma unroll
    for (int mt = 0; mt < 2; mt++) {
        int r_lo = row0 + wm * 32 + mt * 16 + g;
        #pragma unroll
        for (int j = 0; j < 8; j++) {
            int c = col0 + wn * 64 + j * 8 + tq;
            float b0 = bias[c], b1 = bias[c + 1];
            float v00 = acc[mt][j][0] + b0, v01 = acc[mt][j][1] + b1;
            float v10 = acc[mt][j][2] + b0, v11 = acc[mt][j][3] + b1;
            if (job) {
                oa[(size_t)r_lo * N + c]           = __float2half(v00);
                oa[(size_t)r_lo * N + c + 1]       = __float2half(v01);
                oa[(size_t)(r_lo + 8) * N + c]     = __float2half(v10);
                oa[(size_t)(r_lo + 8) * N + c + 1] = __float2half(v11);
            } else {
                valueh[(size_t)r_lo * N + c]           = __float2half(v00);
                valueh[(size_t)r_lo * N + c + 1]       = __float2half(v01);
                valueh[(size_t)(r_lo + 8) * N + c]     = __float2half(v10);
                valueh[(size_t)(r_lo + 8) * N + c + 1] = __float2half(v11);
            }
        }
    }
}

// ---- fused out-projection + residual + LayerNorm: BM=32, BN=256 ------------
#define OB_STRIDE 264
#define XB_STRIDE 264
struct OutSmem {
    __half As[3][32][AS_STRIDE];
    __half Bs[3][GBK][OB_STRIDE];
};
#define OUT_SMEM_BYTES 58368

__global__ __launch_bounds__(256)
void hgemm_out_ln(const __half* __restrict__ A, const __half* __restrict__ B,
                  const float* __restrict__ bias,
                  const float* __restrict__ src,
                  const float* __restrict__ gamma,
                  const float* __restrict__ beta,
                  float* __restrict__ out) {
    extern __shared__ char smem_raw[];
    OutSmem& sm = *(OutSmem*)smem_raw;
    float* xbuf = (float*)smem_raw;

    const int tid  = threadIdx.x;
    const int lane = tid & 31;
    const int warp = tid >> 5;
    const int wm = warp >> 2;
    const int wn = warp & 3;
    const int row0 = blockIdx.x * 32;

    const int a_r = (tid & 127) >> 2;
    const int a_c = (tid & 3) << 3;
    const int b_r = tid >> 5;
    const int b_c = (tid & 31) << 3;

    const __half* Aptr = A + (size_t)row0 * 256;

    auto issue_stage = [&](int s, int k0) {
        if (tid < 128)
            cp16((unsigned)__cvta_generic_to_shared(&sm.As[s][a_r][a_c]),
                 Aptr + (size_t)a_r * 256 + k0 + a_c);
        #pragma unroll
        for (int rr = 0; rr < 4; rr++)
            cp16((unsigned)__cvta_generic_to_shared(&sm.Bs[s][b_r + rr * 8][b_c]),
                 B + (size_t)(k0 + b_r + rr * 8) * 256 + b_c);
    };

    issue_stage(0, 0);   cp_commit();
    issue_stage(1, GBK); cp_commit();

    // preload src rows for phase 2 (hidden behind mainloop)
    float4 spre[4][2];
    #pragma unroll
    for (int i = 0; i < 4; i++) {
        int rg = row0 + warp * 4 + i;
        spre[i][0] = *(const float4*)&src[(size_t)rg * 256 + lane * 8];
        spre[i][1] = *(const float4*)&src[(size_t)rg * 256 + lane * 8 + 4];
    }

    float acc[8][4] = {};
    const int a_lrow = lane & 15;
    const int a_lcol = (lane >> 4) << 3;

    #pragma unroll 1
    for (int t = 0; t < KITERS; t++) {
        const int sb = t % 3;
        cp_wait<1>();
        __syncthreads();

        if (t + 2 < KITERS) issue_stage((t + 2) % 3, (t + 2) * GBK);
        cp_commit();

        #pragma unroll
        for (int ks = 0; ks < 2; ks++) {
            const int kk = ks * 16;
            unsigned af[4], bf[8][2];
            {
                unsigned addr = (unsigned)__cvta_generic_to_shared(
                    &sm.As[sb][wm * 16 + a_lrow][kk + a_lcol]);
                ldm_x4(af[0], af[1], af[2], af[3], addr);
            }
            #pragma unroll
            for (int nt = 0; nt < 4; nt++) {
                unsigned addr = (unsigned)__cvta_generic_to_shared(
                    &sm.Bs[sb][kk + a_lrow][wn * 64 + nt * 16 + a_lcol]);
                unsigned r0, r1, r2, r3;
                ldm_x4_t(r0, r1, r2, r3, addr);
                bf[nt * 2 + 0][0] = r0; bf[nt * 2 + 0][1] = r1;
                bf[nt * 2 + 1][0] = r2; bf[nt * 2 + 1][1] = r3;
            }
            #pragma unroll
            for (int j = 0; j < 8; j++)
                mma16816(acc[j][0], acc[j][1], acc[j][2], acc[j][3],
                         af[0], af[1], af[2], af[3], bf[j][0], bf[j][1]);
        }
    }

    cp_wait<0>();
    __syncthreads();

    const int g  = lane >> 2;
    const int tq = (lane & 3) << 1;
    {
        int rl = wm * 16 + g;
        #pragma unroll
        for (int j = 0; j < 8; j++) {
            int c = wn * 64 + j * 8 + tq;
            float b0 = bias[c], b1 = bias[c + 1];
            float2 lo = {acc[j][0] + b0, acc[j][1] + b1};
            float2 hi = {acc[j][2] + b0, acc[j][3] + b1};
            *(float2*)&xbuf[rl * XB_STRIDE + c]       = lo;
            *(float2*)&xbuf[(rl + 8) * XB_STRIDE + c] = hi;
        }
    }
    __syncthreads();

    float4 gm0 = *(const float4*)&gamma[lane * 8];
    float4 gm1 = *(const float4*)&gamma[lane * 8 + 4];
    float4 bt0 = *(const float4*)&beta[lane * 8];
    float4 bt1 = *(const float4*)&beta[lane * 8 + 4];

    #pragma unroll
    for (int i = 0; i < 4; i++) {
        int rl = warp * 4 + i;
        int rg = row0 + rl;
        float4 x0 = *(float4*)&xbuf[rl * XB_STRIDE + lane * 8];
        float4 x1 = *(float4*)&xbuf[rl * XB_STRIDE + lane * 8 + 4];
        float4 s0 = spre[i][0];
        float4 s1 = spre[i][1];
        float x[8] = {x0.x + s0.x, x0.y + s0.y, x0.z + s0.z, x0.w + s0.w,
                      x1.x + s1.x, x1.y + s1.y, x1.z + s1.z, x1.w + s1.w};

        float sum = 0.f;
        #pragma unroll
        for (int k = 0; k < 8; k++) sum += x[k];
        #pragma unroll
        for (int o = 16; o > 0; o >>= 1) sum += __shfl_xor_sync(0xffffffffu, sum, o);
        float mean = sum * (1.f / 256.f);

        float v = 0.f;
        #pragma unroll
        for (int k = 0; k < 8; k++) { float d = x[k] - mean; v += d * d; }
        #pragma unroll
        for (int o = 16; o > 0; o >>= 1) v += __shfl_xor_sync(0xffffffffu, v, o);
        float rstd = rsqrtf(v * (1.f / 256.f) + 1e-5f);

        float4 o0 = {(x[0] - mean) * rstd * gm0.x + bt0.x,
                     (x[1] - mean) * rstd * gm0.y + bt0.y,
                     (x[2] - mean) * rstd * gm0.z + bt0.z,
                     (x[3] - mean) * rstd * gm0.w + bt0.w};
        float4 o1 = {(x[4] - mean) * rstd * gm1.x + bt1.x,
                     (x[5] - mean) * rstd * gm1.y + bt1.y,
                     (x[6] - mean) * rstd * gm1.z + bt1.z,
                     (x[7] - mean) * rstd * gm1.w + bt1.w};
        *(float4*)&out[(size_t)rg * 256 + lane * 8]     = o0;
        *(float4*)&out[(size_t)rg * 256 + lane * 8 + 4] = o1;
    }
}

// ---------------- sampler (oa now fp16) --------------------------------------
__global__ __launch_bounds__(256)
void sample_kernel(const float* __restrict__ refpts,
                   const __half* __restrict__ oa,
                   const __half* __restrict__ value,
                   __half* __restrict__ out) {
    const int tid  = threadIdx.x;
    const int warp = tid >> 5;
    const int lane = tid & 31;
    const int sub  = warp >> 2;
    const int h    = warp & 3;
    const int nq   = blockIdx.x * 2 + sub;
    const __half* row = oa + (size_t)nq * NOA;

    // ---- phase 1: lane = point pi ----
    __half2 offh = ((const __half2*)row)[h * 32 + lane];
    float2 off   = __half22float2(offh);
    float logit  = __half2float(row[HLP2 + h * 32 + lane]);

    float m = logit;
    #pragma unroll
    for (int o = 16; o > 0; o >>= 1) m = fmaxf(m, __shfl_xor_sync(0xffffffffu, m, o));
    float e = expf(logit - m);
    float s = e;
    #pragma unroll
    for (int o = 16; o > 0; o >>= 1) s += __shfl_xor_sync(0xffffffffu, s, o);
    float aw = e / s;

    float refv = (lane < 8) ? refpts[(size_t)nq * 8 + lane] : 0.f;
    const int l  = lane >> 3;
    const int Wl = 64 >> l;
    const int lvlS[4] = {0, 4096, 5120, 5376};
    const int base = lvlS[l];
    float rx = __shfl_sync(0xffffffffu, refv, l * 2 + 0);
    float ry = __shfl_sync(0xffffffffu, refv, l * 2 + 1);

    float gx = rx * (float)Wl - 0.5f + off.x;
    float gy = ry * (float)Wl - 0.5f + off.y;
    float x0f = floorf(gx), y0f = floorf(gy);
    int x0 = (int)x0f, y0 = (int)y0f;
    float wx1 = gx - x0f, wy1 = gy - y0f;
    float wx0 = 1.f - wx1, wy0 = 1.f - wy1;

    bool xin0 = (x0 >= 0) & (x0 < Wl);
    bool xin1 = (x0 + 1 >= 0) & (x0 + 1 < Wl);
    bool yin0 = (y0 >= 0) & (y0 < Wl);
    bool yin1 = (y0 + 1 >= 0) & (y0 + 1 < Wl);
    int xc0 = min(max(x0, 0), Wl - 1);
    int xc1 = min(max(x0 + 1, 0), Wl - 1);
    int yc0 = min(max(y0, 0), Wl - 1);
    int yc1 = min(max(y0 + 1, 0), Wl - 1);

    unsigned idxA = (unsigned)(base + yc0 * Wl + xc0)
                  | ((unsigned)(base + yc0 * Wl + xc1) << 16);
    unsigned idxB = (unsigned)(base + yc1 * Wl + xc0)
                  | ((unsigned)(base + yc1 * Wl + xc1) << 16);

    float f00 = (yin0 && xin0) ? aw * wy0 * wx0 : 0.f;
    float f01 = (yin0 && xin1) ? aw * wy0 * wx1 : 0.f;
    float f10 = (yin1 && xin0) ? aw * wy1 * wx0 : 0.f;
    float f11 = (yin1 && xin1) ? aw * wy1 * wx1 : 0.f;
    __half2 hw00 = __float2half2_rn(f00);
    __half2 hw01 = __float2half2_rn(f01);
    __half2 hw10 = __float2half2_rn(f10);
    __half2 hw11 = __float2half2_rn(f11);
    unsigned uw00 = *(unsigned*)&hw00, uw01 = *(unsigned*)&hw01;
    unsigned uw10 = *(unsigned*)&hw10, uw11 = *(unsigned*)&hw11;

    // ---- phase 2 ----
    const int g = lane >> 3;
    const int j = lane & 7;
    const uint4* vgh = (const uint4*)value + (size_t)(nq / LQ) * LIN * 32 + h * 8 + j;

    float acc[8] = {};
    __half2 hacc[4] = {{__float2half(0.f), __float2half(0.f)},
                       {__float2half(0.f), __float2half(0.f)},
                       {__float2half(0.f), __float2half(0.f)},
                       {__float2half(0.f), __float2half(0.f)}};

    #pragma unroll
    for (int pp = 0; pp < 8; pp++) {
        const int pi = pp * 4 + g;
        unsigned pA = __shfl_sync(0xffffffffu, idxA, pi);
        unsigned pB = __shfl_sync(0xffffffffu, idxB, pi);
        unsigned w00 = __shfl_sync(0xffffffffu, uw00, pi);
        unsigned w01 = __shfl_sync(0xffffffffu, uw01, pi);
        unsigned w10 = __shfl_sync(0xffffffffu, uw10, pi);
        unsigned w11 = __shfl_sync(0xffffffffu, uw11, pi);

        uint4 c00 = vgh[(size_t)(pA & 0xFFFFu) * 32];
        uint4 c01 = vgh[(size_t)(pA >> 16) * 32];
        uint4 c10 = vgh[(size_t)(pB & 0xFFFFu) * 32];
        uint4 c11 = vgh[(size_t)(pB >> 16) * 32];

        __half2 hw00v = *(__half2*)&w00, hw01v = *(__half2*)&w01;
        __half2 hw10v = *(__half2*)&w10, hw11v = *(__half2*)&w11;

        const unsigned* u00 = (const unsigned*)&c00;
        const unsigned* u01 = (const unsigned*)&c01;
        const unsigned* u10 = (const unsigned*)&c10;
        const unsigned* u11 = (const unsigned*)&c11;
        #pragma unroll
        for (int k = 0; k < 4; k++) {
            __half2 t = __hmul2(*(const __half2*)&u00[k], hw00v);
            t = __hfma2(*(const __half2*)&u01[k], hw01v, t);
            t = __hfma2(*(const __half2*)&u10[k], hw10v, t);
            t = __hfma2(*(const __half2*)&u11[k], hw11v, t);
            hacc[k] = __hadd2(hacc[k], t);
        }
        if (pp == 3 || pp == 7) {
            #pragma unroll
            for (int k = 0; k < 4; k++) {
                float2 f = __half22float2(hacc[k]);
                acc[2 * k]     += f.x;
                acc[2 * k + 1] += f.y;
                hacc[k] = __half2{__float2half(0.f), __float2half(0.f)};
            }
        }
    }

    #pragma unroll
    for (int i = 0; i < 8; i++) {
        acc[i] += __shfl_xor_sync(0xffffffffu, acc[i], 8);
        acc[i] += __shfl_xor_sync(0xffffffffu, acc[i], 16);
    }

    if (lane < 8) {
        __half2 h0 = __floats2half2_rn(acc[0], acc[1]);
        __half2 h1 = __floats2half2_rn(acc[2], acc[3]);
        __half2 h2 = __floats2half2_rn(acc[4], acc[5]);
        __half2 h3 = __floats2half2_rn(acc[6], acc[7]);
        uint4 o;
        o.x = *(unsigned*)&h0; o.y = *(unsigned*)&h1;
        o.z = *(unsigned*)&h2; o.w = *(unsigned*)&h3;
        ((uint4*)(out + (size_t)nq * CC + h * HD))[lane] = o;
    }
}

// ---------------- launcher --------------------------------------------------
extern "C" void kernel_launch(void* const* d_in, const int* in_sizes, int n_in,
                              void* d_out, int out_size) {
    const float* src_feat   = (const float*)d_in[0];
    const float* refpts     = (const float*)d_in[1];
    const float* key_feat   = (const float*)d_in[2];
    const float* query_pos  = (const float*)d_in[5];
    const float* W_value    = (const float*)d_in[6];
    const float* b_value    = (const float*)d_in[7];
    const float* W_off      = (const float*)d_in[8];
    const float* b_off      = (const float*)d_in[9];
    const float* W_attn     = (const float*)d_in[10];
    const float* b_attn     = (const float*)d_in[11];
    const float* W_out      = (const float*)d_in[12];
    const float* b_out      = (const float*)d_in[13];
    const float* ln_g       = (const float*)d_in[14];
    const float* ln_b       = (const float*)d_in[15];
    float* out = (float*)d_out;

    __half *qh, *keyh, *valueh, *oah, *Wvh, *Woah, *Woh, *sampledh;
    float *boa;
    cudaGetSymbolAddress((void**)&qh,       g_q_h);
    cudaGetSymbolAddress((void**)&keyh,     g_key_h);
    cudaGetSymbolAddress((void**)&valueh,   g_value_h);
    cudaGetSymbolAddress((void**)&oah,      g_oa_h);
    cudaGetSymbolAddress((void**)&Wvh,      g_Wv_h);
    cudaGetSymbolAddress((void**)&Woah,     g_Woa_h);
    cudaGetSymbolAddress((void**)&Woh,      g_Wo_h);
    cudaGetSymbolAddress((void**)&boa,      g_boa);
    cudaGetSymbolAddress((void**)&sampledh, g_sampled_h);

    cudaFuncSetAttribute(hgemm_front,
                         cudaFuncAttributeMaxDynamicSharedMemorySize,
                         FRONT_SMEM_BYTES);
    cudaFuncSetAttribute(hgemm_out_ln,
                         cudaFuncAttributeMaxDynamicSharedMemorySize,
                         OUT_SMEM_BYTES);

    prep_kernel<<<(2 * N8 + WPREP + 255) / 256, 256>>>(
        src_feat, query_pos, key_feat, W_value, W_off, W_attn, b_off, b_attn,
        W_out, qh, keyh, Wvh, Woah, Woh, boa);

    hgemm_front<<<dim3(NKV / 64, 5), 128, FRONT_SMEM_BYTES>>>(
        keyh, Wvh, b_value, valueh, qh, Woah, boa, oah);

    sample_kernel<<<NQ / 2, 256>>>(refpts, oah, valueh, sampledh);

    hgemm_out_ln<<<NQ / 32, 256, OUT_SMEM_BYTES>>>(sampledh, Woh, b_out,
                                                   src_feat, ln_g, ln_b, out);
}

// round 13
// speedup vs baseline: 1.0189x; 1.0189x over previous
#include <cuda_runtime.h>
#include <cuda_fp16.h>
#include <math.h>

// ---------------- problem constants ----------------------------------------
#define NB   2
#define LQ   5440
#define CC   256
#define HH   4
#define LL   4
#define PP   8
#define HD   64
#define LIN  5440
#define NQ   (NB * LQ)   // 10880
#define NKV  (NB * LIN)  // 10880
#define HLP  128
#define HLP2 256
#define NOA  384

// ---------------- scratch ---------------------------------------------------
__device__ __half g_q_h[NQ * CC];
__device__ __half g_key_h[NKV * CC];
__device__ __half g_value_h[NKV * CC];
__device__ __half g_oa_h[NQ * NOA];
__device__ __half g_Wv_h[CC * CC];
__device__ __half g_Woa_h[CC * NOA];
__device__ __half g_Wo_h[CC * CC];
__device__ float  g_boa[NOA];
__device__ __half g_sampled_h[NQ * CC];

// ---------------- single prep kernel ----------------------------------------
#define N8 (NQ * CC / 8)
#define WPREP (CC * NOA)
__global__ __launch_bounds__(256)
void prep_kernel(const float* __restrict__ src,
                 const float* __restrict__ pos,
                 const float* __restrict__ key,
                 const float* __restrict__ Wv,
                 const float* __restrict__ Woff,
                 const float* __restrict__ Wattn,
                 const float* __restrict__ boff,
                 const float* __restrict__ battn,
                 const float* __restrict__ Wo,
                 __half* __restrict__ qh,
                 __half* __restrict__ keyh,
                 __half* __restrict__ Wvh,
                 __half* __restrict__ Woah,
                 __half* __restrict__ Woh,
                 float* __restrict__ boa) {
    int i = blockIdx.x * blockDim.x + threadIdx.x;
    if (i < N8) {
        float4 s0 = ((const float4*)src)[i * 2];
        float4 s1 = ((const float4*)src)[i * 2 + 1];
        float4 p0 = ((const float4*)pos)[i * 2];
        float4 p1 = ((const float4*)pos)[i * 2 + 1];
        __half2 h0 = __floats2half2_rn(s0.x + p0.x, s0.y + p0.y);
        __half2 h1 = __floats2half2_rn(s0.z + p0.z, s0.w + p0.w);
        __half2 h2 = __floats2half2_rn(s1.x + p1.x, s1.y + p1.y);
        __half2 h3 = __floats2half2_rn(s1.z + p1.z, s1.w + p1.w);
        uint4 o; o.x = *(unsigned*)&h0; o.y = *(unsigned*)&h1;
        o.z = *(unsigned*)&h2; o.w = *(unsigned*)&h3;
        ((uint4*)qh)[i] = o;
    } else if (i < 2 * N8) {
        int j = i - N8;
        float4 k0 = ((const float4*)key)[j * 2];
        float4 k1 = ((const float4*)key)[j * 2 + 1];
        __half2 h0 = __floats2half2_rn(k0.x, k0.y);
        __half2 h1 = __floats2half2_rn(k0.z, k0.w);
        __half2 h2 = __floats2half2_rn(k1.x, k1.y);
        __half2 h3 = __floats2half2_rn(k1.z, k1.w);
        uint4 o; o.x = *(unsigned*)&h0; o.y = *(unsigned*)&h1;
        o.z = *(unsigned*)&h2; o.w = *(unsigned*)&h3;
        ((uint4*)keyh)[j] = o;
    } else {
        int j = i - 2 * N8;
        if (j < WPREP) {
            if (j < CC * CC) {
                Wvh[j] = __float2half(Wv[j]);
                Woh[j] = __float2half(Wo[j]);
            }
            int k = j / NOA, n = j % NOA;
            float w = (n < HLP2) ? Woff[k * HLP2 + n] : Wattn[k * HLP + (n - HLP2)];
            Woah[j] = __float2half(w);
            if (j < NOA) boa[j] = (j < HLP2) ? boff[j] : battn[j - HLP2];
        }
    }
}

// ---------------- GEMM primitives -------------------------------------------
#define GBK 32
#define KITERS 8
#define AS_STRIDE 40

__device__ __forceinline__ void cp16(unsigned dst, const void* src) {
    asm volatile("cp.async.cg.shared.global [%0], [%1], 16;\n" :: "r"(dst), "l"(src));
}
__device__ __forceinline__ void cp_commit() {
    asm volatile("cp.async.commit_group;\n");
}
template <int N>
__device__ __forceinline__ void cp_wait() {
    asm volatile("cp.async.wait_group %0;\n" :: "n"(N));
}
__device__ __forceinline__ void ldm_x4(unsigned& r0, unsigned& r1,
                                       unsigned& r2, unsigned& r3, unsigned addr) {
    asm volatile("ldmatrix.sync.aligned.m8n8.x4.shared.b16 {%0,%1,%2,%3}, [%4];"
                 : "=r"(r0), "=r"(r1), "=r"(r2), "=r"(r3) : "r"(addr));
}
__device__ __forceinline__ void ldm_x4_t(unsigned& r0, unsigned& r1,
                                         unsigned& r2, unsigned& r3, unsigned addr) {
    asm volatile("ldmatrix.sync.aligned.m8n8.x4.trans.shared.b16 {%0,%1,%2,%3}, [%4];"
                 : "=r"(r0), "=r"(r1), "=r"(r2), "=r"(r3) : "r"(addr));
}
__device__ __forceinline__ void mma16816(float& c0, float& c1, float& c2, float& c3,
                                         unsigned a0, unsigned a1, unsigned a2, unsigned a3,
                                         unsigned b0, unsigned b1) {
    asm volatile(
        "mma.sync.aligned.m16n8k16.row.col.f32.f16.f16.f32 "
        "{%0,%1,%2,%3}, {%4,%5,%6,%7}, {%8,%9}, {%0,%1,%2,%3};"
        : "+f"(c0), "+f"(c1), "+f"(c2), "+f"(c3)
        : "r"(a0), "r"(a1), "r"(a2), "r"(a3), "r"(b0), "r"(b1));
}

// ---- front GEMM: BM=64, BN=128, 128 thr (4 warps, warp tile 32x64), 3-stage
#define FB_STRIDE 136
struct FrontSmem {
    __half As[3][64][AS_STRIDE];
    __half Bs[3][GBK][FB_STRIDE];
};

__global__ __launch_bounds__(128, 3)
void hgemm_front(const __half* __restrict__ keyh, const __half* __restrict__ Wvh,
                 const float* __restrict__ bval,  __half* __restrict__ valueh,
                 const __half* __restrict__ qh,   const __half* __restrict__ Woah,
                 const float* __restrict__ boa,   __half* __restrict__ oa) {
    __shared__ FrontSmem sm;
    const int tid  = threadIdx.x;
    const int lane = tid & 31;
    const int warp = tid >> 5;
    const int wm = warp >> 1;
    const int wn = warp & 1;

    const int job  = (blockIdx.y < 2) ? 0 : 1;
    const int coly = job ? (blockIdx.y - 2) : blockIdx.y;
    const int N    = job ? NOA : CC;
    const __half* A = job ? qh : keyh;
    const __half* B = job ? Woah : Wvh;
    const float* bias = job ? boa : bval;

    const int row0 = blockIdx.x * 64;
    const int col0 = coly * 128;

    const int a_r = tid >> 2;
    const int a_c = (tid & 3) << 3;
    const int b_r = tid >> 4;
    const int b_c = (tid & 15) << 3;

    const __half* Aptr = A + (size_t)row0 * 256;
    const __half* Bptr = B + col0;

    auto issue_stage = [&](int s, int k0) {
        cp16((unsigned)__cvta_generic_to_shared(&sm.As[s][a_r][a_c]),
             Aptr + (size_t)a_r * 256 + k0 + a_c);
        cp16((unsigned)__cvta_generic_to_shared(&sm.As[s][a_r + 32][a_c]),
             Aptr + (size_t)(a_r + 32) * 256 + k0 + a_c);
        #pragma unroll
        for (int rr = 0; rr < 4; rr++)
            cp16((unsigned)__cvta_generic_to_shared(&sm.Bs[s][b_r + rr * 8][b_c]),
                 Bptr + (size_t)(k0 + b_r + rr * 8) * N + b_c);
    };

    issue_stage(0, 0);   cp_commit();
    issue_stage(1, GBK); cp_commit();

    float acc[2][8][4] = {};
    const int a_lrow = lane & 15;
    const int a_lcol = (lane >> 4) << 3;

    #pragma unroll 1
    for (int t = 0; t < KITERS; t++) {
        const int sb = t % 3;
        cp_wait<1>();
        __syncthreads();

        if (t + 2 < KITERS) issue_stage((t + 2) % 3, (t + 2) * GBK);
        cp_commit();

        #pragma unroll
        for (int ks = 0; ks < 2; ks++) {
            const int kk = ks * 16;
            unsigned af[2][4], bf[8][2];
            #pragma unroll
            for (int mt = 0; mt < 2; mt++) {
                unsigned addr = (unsigned)__cvta_generic_to_shared(
                    &sm.As[sb][wm * 32 + mt * 16 + a_lrow][kk + a_lcol]);
                ldm_x4(af[mt][0], af[mt][1], af[mt][2], af[mt][3], addr);
            }
            #pragma unroll
            for (int nt = 0; nt < 4; nt++) {
                unsigned addr = (unsigned)__cvta_generic_to_shared(
                    &sm.Bs[sb][kk + a_lrow][wn * 64 + nt * 16 + a_lcol]);
                unsigned r0, r1, r2, r3;
                ldm_x4_t(r0, r1, r2, r3, addr);
                bf[nt * 2 + 0][0] = r0; bf[nt * 2 + 0][1] = r1;
                bf[nt * 2 + 1][0] = r2; bf[nt * 2 + 1][1] = r3;
            }
            #pragma unroll
            for (int mt = 0; mt < 2; mt++)
                #pragma unroll
                for (int j = 0; j < 8; j++)
                    mma16816(acc[mt][j][0], acc[mt][j][1], acc[mt][j][2], acc[mt][j][3],
                             af[mt][0], af[mt][1], af[mt][2], af[mt][3],
                             bf[j][0], bf[j][1]);
        }
    }

    const int g  = lane >> 2;
    const int tq = (lane & 3) << 1;
    #pragma unroll
    for (int mt = 0; mt < 2; mt++) {
        int r_lo = row0 + wm * 32 + mt * 16 + g;
        #pragma unroll
        for (int j = 0; j < 8; j++) {
            int c = col0 + wn * 64 + j * 8 + tq;
            float b0 = bias[c], b1 = bias[c + 1];
            float v00 = acc[mt][j][0] + b0, v01 = acc[mt][j][1] + b1;
            float v10 = acc[mt][j][2] + b0, v11 = acc[mt][j][3] + b1;
            if (job) {
                oa[(size_t)r_lo * N + c]           = __float2half(v00);
                oa[(size_t)r_lo * N + c + 1]       = __float2half(v01);
                oa[(size_t)(r_lo + 8) * N + c]     = __float2half(v10);
                oa[(size_t)(r_lo + 8) * N + c + 1] = __float2half(v11);
            } else {
                valueh[(size_t)r_lo * N + c]           = __float2half(v00);
                valueh[(size_t)r_lo * N + c + 1]       = __float2half(v01);
                valueh[(size_t)(r_lo + 8) * N + c]     = __float2half(v10);
                valueh[(size_t)(r_lo + 8) * N + c + 1] = __float2half(v11);
            }
        }
    }
}

// ---- fused out-projection + residual + LayerNorm: BM=32, BN=256 ------------
// (exact R11 version: no src preload, 64 regs, 2 CTA/SM)
#define OB_STRIDE 264
#define XB_STRIDE 264
struct OutSmem {
    __half As[3][32][AS_STRIDE];
    __half Bs[3][GBK][OB_STRIDE];
};
#define OUT_SMEM_BYTES 58368

__global__ __launch_bounds__(256)
void hgemm_out_ln(const __half* __restrict__ A, const __half* __restrict__ B,
                  const float* __restrict__ bias,
                  const float* __restrict__ src,
                  const float* __restrict__ gamma,
                  const float* __restrict__ beta,
                  float* __restrict__ out) {
    extern __shared__ char smem_raw[];
    OutSmem& sm = *(OutSmem*)smem_raw;
    float* xbuf = (float*)smem_raw;

    const int tid  = threadIdx.x;
    const int lane = tid & 31;
    const int warp = tid >> 5;
    const int wm = warp >> 2;
    const int wn = warp & 3;
    const int row0 = blockIdx.x * 32;

    const int a_r = (tid & 127) >> 2;
    const int a_c = (tid & 3) << 3;
    const int b_r = tid >> 5;
    const int b_c = (tid & 31) << 3;

    const __half* Aptr = A + (size_t)row0 * 256;

    auto issue_stage = [&](int s, int k0) {
        if (tid < 128)
            cp16((unsigned)__cvta_generic_to_shared(&sm.As[s][a_r][a_c]),
                 Aptr + (size_t)a_r * 256 + k0 + a_c);
        #pragma unroll
        for (int rr = 0; rr < 4; rr++)
            cp16((unsigned)__cvta_generic_to_shared(&sm.Bs[s][b_r + rr * 8][b_c]),
                 B + (size_t)(k0 + b_r + rr * 8) * 256 + b_c);
    };

    issue_stage(0, 0);   cp_commit();
    issue_stage(1, GBK); cp_commit();

    float acc[8][4] = {};
    const int a_lrow = lane & 15;
    const int a_lcol = (lane >> 4) << 3;

    #pragma unroll 1
    for (int t = 0; t < KITERS; t++) {
        const int sb = t % 3;
        cp_wait<1>();
        __syncthreads();

        if (t + 2 < KITERS) issue_stage((t + 2) % 3, (t + 2) * GBK);
        cp_commit();

        #pragma unroll
        for (int ks = 0; ks < 2; ks++) {
            const int kk = ks * 16;
            unsigned af[4], bf[8][2];
            {
                unsigned addr = (unsigned)__cvta_generic_to_shared(
                    &sm.As[sb][wm * 16 + a_lrow][kk + a_lcol]);
                ldm_x4(af[0], af[1], af[2], af[3], addr);
            }
            #pragma unroll
            for (int nt = 0; nt < 4; nt++) {
                unsigned addr = (unsigned)__cvta_generic_to_shared(
                    &sm.Bs[sb][kk + a_lrow][wn * 64 + nt * 16 + a_lcol]);
                unsigned r0, r1, r2, r3;
                ldm_x4_t(r0, r1, r2, r3, addr);
                bf[nt * 2 + 0][0] = r0; bf[nt * 2 + 0][1] = r1;
                bf[nt * 2 + 1][0] = r2; bf[nt * 2 + 1][1] = r3;
            }
            #pragma unroll
            for (int j = 0; j < 8; j++)
                mma16816(acc[j][0], acc[j][1], acc[j][2], acc[j][3],
                         af[0], af[1], af[2], af[3], bf[j][0], bf[j][1]);
        }
    }

    cp_wait<0>();
    __syncthreads();

    const int g  = lane >> 2;
    const int tq = (lane & 3) << 1;
    {
        int rl = wm * 16 + g;
        #pragma unroll
        for (int j = 0; j < 8; j++) {
            int c = wn * 64 + j * 8 + tq;
            float b0 = bias[c], b1 = bias[c + 1];
            float2 lo = {acc[j][0] + b0, acc[j][1] + b1};
            float2 hi = {acc[j][2] + b0, acc[j][3] + b1};
            *(float2*)&xbuf[rl * XB_STRIDE + c]       = lo;
            *(float2*)&xbuf[(rl + 8) * XB_STRIDE + c] = hi;
        }
    }
    __syncthreads();

    float4 gm0 = *(const float4*)&gamma[lane * 8];
    float4 gm1 = *(const float4*)&gamma[lane * 8 + 4];
    float4 bt0 = *(const float4*)&beta[lane * 8];
    float4 bt1 = *(const float4*)&beta[lane * 8 + 4];

    #pragma unroll 1
    for (int i = 0; i < 4; i++) {
        int rl = warp * 4 + i;
        int rg = row0 + rl;
        float4 x0 = *(float4*)&xbuf[rl * XB_STRIDE + lane * 8];
        float4 x1 = *(float4*)&xbuf[rl * XB_STRIDE + lane * 8 + 4];
        float4 s0 = *(const float4*)&src[(size_t)rg * 256 + lane * 8];
        float4 s1 = *(const float4*)&src[(size_t)rg * 256 + lane * 8 + 4];
        float x[8] = {x0.x + s0.x, x0.y + s0.y, x0.z + s0.z, x0.w + s0.w,
                      x1.x + s1.x, x1.y + s1.y, x1.z + s1.z, x1.w + s1.w};

        float sum = 0.f;
        #pragma unroll
        for (int k = 0; k < 8; k++) sum += x[k];
        #pragma unroll
        for (int o = 16; o > 0; o >>= 1) sum += __shfl_xor_sync(0xffffffffu, sum, o);
        float mean = sum * (1.f / 256.f);

        float v = 0.f;
        #pragma unroll
        for (int k = 0; k < 8; k++) { float d = x[k] - mean; v += d * d; }
        #pragma unroll
        for (int o = 16; o > 0; o >>= 1) v += __shfl_xor_sync(0xffffffffu, v, o);
        float rstd = rsqrtf(v * (1.f / 256.f) + 1e-5f);

        float4 o0 = {(x[0] - mean) * rstd * gm0.x + bt0.x,
                     (x[1] - mean) * rstd * gm0.y + bt0.y,
                     (x[2] - mean) * rstd * gm0.z + bt0.z,
                     (x[3] - mean) * rstd * gm0.w + bt0.w};
        float4 o1 = {(x[4] - mean) * rstd * gm1.x + bt1.x,
                     (x[5] - mean) * rstd * gm1.y + bt1.y,
                     (x[6] - mean) * rstd * gm1.z + bt1.z,
                     (x[7] - mean) * rstd * gm1.w + bt1.w};
        *(float4*)&out[(size_t)rg * 256 + lane * 8]     = o0;
        *(float4*)&out[(size_t)rg * 256 + lane * 8 + 4] = o1;
    }
}

// ---------------- sampler (fp16 oa) ------------------------------------------
__global__ __launch_bounds__(256)
void sample_kernel(const float* __restrict__ refpts,
                   const __half* __restrict__ oa,
                   const __half* __restrict__ value,
                   __half* __restrict__ out) {
    const int tid  = threadIdx.x;
    const int warp = tid >> 5;
    const int lane = tid & 31;
    const int sub  = warp >> 2;
    const int h    = warp & 3;
    const int nq   = blockIdx.x * 2 + sub;
    const __half* row = oa + (size_t)nq * NOA;

    // ---- phase 1: lane = point pi ----
    __half2 offh = ((const __half2*)row)[h * 32 + lane];
    float2 off   = __half22float2(offh);
    float logit  = __half2float(row[HLP2 + h * 32 + lane]);

    float m = logit;
    #pragma unroll
    for (int o = 16; o > 0; o >>= 1) m = fmaxf(m, __shfl_xor_sync(0xffffffffu, m, o));
    float e = expf(logit - m);
    float s = e;
    #pragma unroll
    for (int o = 16; o > 0; o >>= 1) s += __shfl_xor_sync(0xffffffffu, s, o);
    float aw = e / s;

    float refv = (lane < 8) ? refpts[(size_t)nq * 8 + lane] : 0.f;
    const int l  = lane >> 3;
    const int Wl = 64 >> l;
    const int lvlS[4] = {0, 4096, 5120, 5376};
    const int base = lvlS[l];
    float rx = __shfl_sync(0xffffffffu, refv, l * 2 + 0);
    float ry = __shfl_sync(0xffffffffu, refv, l * 2 + 1);

    float gx = rx * (float)Wl - 0.5f + off.x;
    float gy = ry * (float)Wl - 0.5f + off.y;
    float x0f = floorf(gx), y0f = floorf(gy);
    int x0 = (int)x0f, y0 = (int)y0f;
    float wx1 = gx - x0f, wy1 = gy - y0f;
    float wx0 = 1.f - wx1, wy0 = 1.f - wy1;

    bool xin0 = (x0 >= 0) & (x0 < Wl);
    bool xin1 = (x0 + 1 >= 0) & (x0 + 1 < Wl);
    bool yin0 = (y0 >= 0) & (y0 < Wl);
    bool yin1 = (y0 + 1 >= 0) & (y0 + 1 < Wl);
    int xc0 = min(max(x0, 0), Wl - 1);
    int xc1 = min(max(x0 + 1, 0), Wl - 1);
    int yc0 = min(max(y0, 0), Wl - 1);
    int yc1 = min(max(y0 + 1, 0), Wl - 1);

    unsigned idxA = (unsigned)(base + yc0 * Wl + xc0)
                  | ((unsigned)(base + yc0 * Wl + xc1) << 16);
    unsigned idxB = (unsigned)(base + yc1 * Wl + xc0)
                  | ((unsigned)(base + yc1 * Wl + xc1) << 16);

    float f00 = (yin0 && xin0) ? aw * wy0 * wx0 : 0.f;
    float f01 = (yin0 && xin1) ? aw * wy0 * wx1 : 0.f;
    float f10 = (yin1 && xin0) ? aw * wy1 * wx0 : 0.f;
    float f11 = (yin1 && xin1) ? aw * wy1 * wx1 : 0.f;
    __half2 hw00 = __float2half2_rn(f00);
    __half2 hw01 = __float2half2_rn(f01);
    __half2 hw10 = __float2half2_rn(f10);
    __half2 hw11 = __float2half2_rn(f11);
    unsigned uw00 = *(unsigned*)&hw00, uw01 = *(unsigned*)&hw01;
    unsigned uw10 = *(unsigned*)&hw10, uw11 = *(unsigned*)&hw11;

    // ---- phase 2 ----
    const int g = lane >> 3;
    const int j = lane & 7;
    const uint4* vgh = (const uint4*)value + (size_t)(nq / LQ) * LIN * 32 + h * 8 + j;

    float acc[8] = {};
    __half2 hacc[4] = {{__float2half(0.f), __float2half(0.f)},
                       {__float2half(0.f), __float2half(0.f)},
                       {__float2half(0.f), __float2half(0.f)},
                       {__float2half(0.f), __float2half(0.f)}};

    #pragma unroll
    for (int pp = 0; pp < 8; pp++) {
        const int pi = pp * 4 + g;
        unsigned pA = __shfl_sync(0xffffffffu, idxA, pi);
        unsigned pB = __shfl_sync(0xffffffffu, idxB, pi);
        unsigned w00 = __shfl_sync(0xffffffffu, uw00, pi);
        unsigned w01 = __shfl_sync(0xffffffffu, uw01, pi);
        unsigned w10 = __shfl_sync(0xffffffffu, uw10, pi);
        unsigned w11 = __shfl_sync(0xffffffffu, uw11, pi);

        uint4 c00 = vgh[(size_t)(pA & 0xFFFFu) * 32];
        uint4 c01 = vgh[(size_t)(pA >> 16) * 32];
        uint4 c10 = vgh[(size_t)(pB & 0xFFFFu) * 32];
        uint4 c11 = vgh[(size_t)(pB >> 16) * 32];

        __half2 hw00v = *(__half2*)&w00, hw01v = *(__half2*)&w01;
        __half2 hw10v = *(__half2*)&w10, hw11v = *(__half2*)&w11;

        const unsigned* u00 = (const unsigned*)&c00;
        const unsigned* u01 = (const unsigned*)&c01;
        const unsigned* u10 = (const unsigned*)&c10;
        const unsigned* u11 = (const unsigned*)&c11;
        #pragma unroll
        for (int k = 0; k < 4; k++) {
            __half2 t = __hmul2(*(const __half2*)&u00[k], hw00v);
            t = __hfma2(*(const __half2*)&u01[k], hw01v, t);
            t = __hfma2(*(const __half2*)&u10[k], hw10v, t);
            t = __hfma2(*(const __half2*)&u11[k], hw11v, t);
            hacc[k] = __hadd2(hacc[k], t);
        }
        if (pp == 3 || pp == 7) {
            #pragma unroll
            for (int k = 0; k < 4; k++) {
                float2 f = __half22float2(hacc[k]);
                acc[2 * k]     += f.x;
                acc[2 * k + 1] += f.y;
                hacc[k] = __half2{__float2half(0.f), __float2half(0.f)};
            }
        }
    }

    #pragma unroll
    for (int i = 0; i < 8; i++) {
        acc[i] += __shfl_xor_sync(0xffffffffu, acc[i], 8);
        acc[i] += __shfl_xor_sync(0xffffffffu, acc[i], 16);
    }

    if (lane < 8) {
        __half2 h0 = __floats2half2_rn(acc[0], acc[1]);
        __half2 h1 = __floats2half2_rn(acc[2], acc[3]);
        __half2 h2 = __floats2half2_rn(acc[4], acc[5]);
        __half2 h3 = __floats2half2_rn(acc[6], acc[7]);
        uint4 o;
        o.x = *(unsigned*)&h0; o.y = *(unsigned*)&h1;
        o.z = *(unsigned*)&h2; o.w = *(unsigned*)&h3;
        ((uint4*)(out + (size_t)nq * CC + h * HD))[lane] = o;
    }
}

// ---------------- launcher --------------------------------------------------
extern "C" void kernel_launch(void* const* d_in, const int* in_sizes, int n_in,
                              void* d_out, int out_size) {
    const float* src_feat   = (const float*)d_in[0];
    const float* refpts     = (const float*)d_in[1];
    const float* key_feat   = (const float*)d_in[2];
    const float* query_pos  = (const float*)d_in[5];
    const float* W_value    = (const float*)d_in[6];
    const float* b_value    = (const float*)d_in[7];
    const float* W_off      = (const float*)d_in[8];
    const float* b_off      = (const float*)d_in[9];
    const float* W_attn     = (const float*)d_in[10];
    const float* b_attn     = (const float*)d_in[11];
    const float* W_out      = (const float*)d_in[12];
    const float* b_out      = (const float*)d_in[13];
    const float* ln_g       = (const float*)d_in[14];
    const float* ln_b       = (const float*)d_in[15];
    float* out = (float*)d_out;

    __half *qh, *keyh, *valueh, *oah, *Wvh, *Woah, *Woh, *sampledh;
    float *boa;
    cudaGetSymbolAddress((void**)&qh,       g_q_h);
    cudaGetSymbolAddress((void**)&keyh,     g_key_h);
    cudaGetSymbolAddress((void**)&valueh,   g_value_h);
    cudaGetSymbolAddress((void**)&oah,      g_oa_h);
    cudaGetSymbolAddress((void**)&Wvh,      g_Wv_h);
    cudaGetSymbolAddress((void**)&Woah,     g_Woa_h);
    cudaGetSymbolAddress((void**)&Woh,      g_Wo_h);
    cudaGetSymbolAddress((void**)&boa,      g_boa);
    cudaGetSymbolAddress((void**)&sampledh, g_sampled_h);

    cudaFuncSetAttribute(hgemm_out_ln,
                         cudaFuncAttributeMaxDynamicSharedMemorySize,
                         OUT_SMEM_BYTES);

    prep_kernel<<<(2 * N8 + WPREP + 255) / 256, 256>>>(
        src_feat, query_pos, key_feat, W_value, W_off, W_attn, b_off, b_attn,
        W_out, qh, keyh, Wvh, Woah, Woh, boa);

    hgemm_front<<<dim3(NKV / 64, 5), 128>>>(keyh, Wvh, b_value, valueh,
                                            qh, Woah, boa, oah);

    sample_kernel<<<NQ / 2, 256>>>(refpts, oah, valueh, sampledh);

    hgemm_out_ln<<<NQ / 32, 256, OUT_SMEM_BYTES>>>(sampledh, Woh, b_out,
                                                   src_feat, ln_g, ln_b, out);
}

// round 14
// speedup vs baseline: 1.0213x; 1.0023x over previous
#include <cuda_runtime.h>
#include <cuda_fp16.h>
#include <math.h>

// ---------------- problem constants ----------------------------------------
#define NB   2
#define LQ   5440
#define CC   256
#define HH   4
#define LL   4
#define PP   8
#define HD   64
#define LIN  5440
#define NQ   (NB * LQ)   // 10880
#define NKV  (NB * LIN)  // 10880
#define HLP  128
#define HLP2 256
#define NOA  384

// ---------------- scratch ---------------------------------------------------
__device__ __half g_q_h[NQ * CC];
__device__ __half g_key_h[NKV * CC];
__device__ __half g_value_h[NKV * CC];
__device__ float  g_oa[NQ * NOA];
__device__ __half g_Wv_h[CC * CC];
__device__ __half g_Woa_h[CC * NOA];
__device__ __half g_Wo_h[CC * CC];
__device__ float  g_boa[NOA];
__device__ __half g_sampled_h[NQ * CC];

// ---------------- single prep kernel ----------------------------------------
#define N8 (NQ * CC / 8)
#define WPREP (CC * NOA)
__global__ __launch_bounds__(256)
void prep_kernel(const float* __restrict__ src,
                 const float* __restrict__ pos,
                 const float* __restrict__ key,
                 const float* __restrict__ Wv,
                 const float* __restrict__ Woff,
                 const float* __restrict__ Wattn,
                 const float* __restrict__ boff,
                 const float* __restrict__ battn,
                 const float* __restrict__ Wo,
                 __half* __restrict__ qh,
                 __half* __restrict__ keyh,
                 __half* __restrict__ Wvh,
                 __half* __restrict__ Woah,
                 __half* __restrict__ Woh,
                 float* __restrict__ boa) {
    int i = blockIdx.x * blockDim.x + threadIdx.x;
    if (i < N8) {
        float4 s0 = ((const float4*)src)[i * 2];
        float4 s1 = ((const float4*)src)[i * 2 + 1];
        float4 p0 = ((const float4*)pos)[i * 2];
        float4 p1 = ((const float4*)pos)[i * 2 + 1];
        __half2 h0 = __floats2half2_rn(s0.x + p0.x, s0.y + p0.y);
        __half2 h1 = __floats2half2_rn(s0.z + p0.z, s0.w + p0.w);
        __half2 h2 = __floats2half2_rn(s1.x + p1.x, s1.y + p1.y);
        __half2 h3 = __floats2half2_rn(s1.z + p1.z, s1.w + p1.w);
        uint4 o; o.x = *(unsigned*)&h0; o.y = *(unsigned*)&h1;
        o.z = *(unsigned*)&h2; o.w = *(unsigned*)&h3;
        ((uint4*)qh)[i] = o;
    } else if (i < 2 * N8) {
        int j = i - N8;
        float4 k0 = ((const float4*)key)[j * 2];
        float4 k1 = ((const float4*)key)[j * 2 + 1];
        __half2 h0 = __floats2half2_rn(k0.x, k0.y);
        __half2 h1 = __floats2half2_rn(k0.z, k0.w);
        __half2 h2 = __floats2half2_rn(k1.x, k1.y);
        __half2 h3 = __floats2half2_rn(k1.z, k1.w);
        uint4 o; o.x = *(unsigned*)&h0; o.y = *(unsigned*)&h1;
        o.z = *(unsigned*)&h2; o.w = *(unsigned*)&h3;
        ((uint4*)keyh)[j] = o;
    } else {
        int j = i - 2 * N8;
        if (j < WPREP) {
            if (j < CC * CC) {
                Wvh[j] = __float2half(Wv[j]);
                Woh[j] = __float2half(Wo[j]);
            }
            int k = j / NOA, n = j % NOA;
            float w = (n < HLP2) ? Woff[k * HLP2 + n] : Wattn[k * HLP + (n - HLP2)];
            Woah[j] = __float2half(w);
            if (j < NOA) boa[j] = (j < HLP2) ? boff[j] : battn[j - HLP2];
        }
    }
}

// ---------------- GEMM primitives -------------------------------------------
#define GBK 32
#define KITERS 8
#define AS_STRIDE 40

__device__ __forceinline__ void cp16(unsigned dst, const void* src) {
    asm volatile("cp.async.cg.shared.global [%0], [%1], 16;\n" :: "r"(dst), "l"(src));
}
__device__ __forceinline__ void cp_commit() {
    asm volatile("cp.async.commit_group;\n");
}
template <int N>
__device__ __forceinline__ void cp_wait() {
    asm volatile("cp.async.wait_group %0;\n" :: "n"(N));
}
__device__ __forceinline__ void ldm_x4(unsigned& r0, unsigned& r1,
                                       unsigned& r2, unsigned& r3, unsigned addr) {
    asm volatile("ldmatrix.sync.aligned.m8n8.x4.shared.b16 {%0,%1,%2,%3}, [%4];"
                 : "=r"(r0), "=r"(r1), "=r"(r2), "=r"(r3) : "r"(addr));
}
__device__ __forceinline__ void ldm_x4_t(unsigned& r0, unsigned& r1,
                                         unsigned& r2, unsigned& r3, unsigned addr) {
    asm volatile("ldmatrix.sync.aligned.m8n8.x4.trans.shared.b16 {%0,%1,%2,%3}, [%4];"
                 : "=r"(r0), "=r"(r1), "=r"(r2), "=r"(r3) : "r"(addr));
}
__device__ __forceinline__ void mma16816(float& c0, float& c1, float& c2, float& c3,
                                         unsigned a0, unsigned a1, unsigned a2, unsigned a3,
                                         unsigned b0, unsigned b1) {
    asm volatile(
        "mma.sync.aligned.m16n8k16.row.col.f32.f16.f16.f32 "
        "{%0,%1,%2,%3}, {%4,%5,%6,%7}, {%8,%9}, {%0,%1,%2,%3};"
        : "+f"(c0), "+f"(c1), "+f"(c2), "+f"(c3)
        : "r"(a0), "r"(a1), "r"(a2), "r"(a3), "r"(b0), "r"(b1));
}

// ---- front GEMM: BM=64, BN=128, 128 thr (4 warps, warp tile 32x64), 3-stage
#define FB_STRIDE 136
struct FrontSmem {
    __half As[3][64][AS_STRIDE];
    __half Bs[3][GBK][FB_STRIDE];
};

__global__ __launch_bounds__(128, 3)
void hgemm_front(const __half* __restrict__ keyh, const __half* __restrict__ Wvh,
                 const float* __restrict__ bval,  __half* __restrict__ valueh,
                 const __half* __restrict__ qh,   const __half* __restrict__ Woah,
                 const float* __restrict__ boa,   float* __restrict__ oa) {
    __shared__ FrontSmem sm;
    const int tid  = threadIdx.x;
    const int lane = tid & 31;
    const int warp = tid >> 5;
    const int wm = warp >> 1;
    const int wn = warp & 1;

    const int job  = (blockIdx.y < 2) ? 0 : 1;
    const int coly = job ? (blockIdx.y - 2) : blockIdx.y;
    const int N    = job ? NOA : CC;
    const __half* A = job ? qh : keyh;
    const __half* B = job ? Woah : Wvh;
    const float* bias = job ? boa : bval;

    const int row0 = blockIdx.x * 64;
    const int col0 = coly * 128;

    const int a_r = tid >> 2;
    const int a_c = (tid & 3) << 3;
    const int b_r = tid >> 4;
    const int b_c = (tid & 15) << 3;

    const __half* Aptr = A + (size_t)row0 * 256;
    const __half* Bptr = B + col0;

    auto issue_stage = [&](int s, int k0) {
        cp16((unsigned)__cvta_generic_to_shared(&sm.As[s][a_r][a_c]),
             Aptr + (size_t)a_r * 256 + k0 + a_c);
        cp16((unsigned)__cvta_generic_to_shared(&sm.As[s][a_r + 32][a_c]),
             Aptr + (size_t)(a_r + 32) * 256 + k0 + a_c);
        #pragma unroll
        for (int rr = 0; rr < 4; rr++)
            cp16((unsigned)__cvta_generic_to_shared(&sm.Bs[s][b_r + rr * 8][b_c]),
                 Bptr + (size_t)(k0 + b_r + rr * 8) * N + b_c);
    };

    issue_stage(0, 0);   cp_commit();
    issue_stage(1, GBK); cp_commit();

    float acc[2][8][4] = {};
    const int a_lrow = lane & 15;
    const int a_lcol = (lane >> 4) << 3;

    #pragma unroll 1
    for (int t = 0; t < KITERS; t++) {
        const int sb = t % 3;
        cp_wait<1>();
        __syncthreads();

        if (t + 2 < KITERS) issue_stage((t + 2) % 3, (t + 2) * GBK);
        cp_commit();

        #pragma unroll
        for (int ks = 0; ks < 2; ks++) {
            const int kk = ks * 16;
            unsigned af[2][4], bf[8][2];
            #pragma unroll
            for (int mt = 0; mt < 2; mt++) {
                unsigned addr = (unsigned)__cvta_generic_to_shared(
                    &sm.As[sb][wm * 32 + mt * 16 + a_lrow][kk + a_lcol]);
                ldm_x4(af[mt][0], af[mt][1], af[mt][2], af[mt][3], addr);
            }
            #pragma unroll
            for (int nt = 0; nt < 4; nt++) {
                unsigned addr = (unsigned)__cvta_generic_to_shared(
                    &sm.Bs[sb][kk + a_lrow][wn * 64 + nt * 16 + a_lcol]);
                unsigned r0, r1, r2, r3;
                ldm_x4_t(r0, r1, r2, r3, addr);
                bf[nt * 2 + 0][0] = r0; bf[nt * 2 + 0][1] = r1;
                bf[nt * 2 + 1][0] = r2; bf[nt * 2 + 1][1] = r3;
            }
            #pragma unroll
            for (int mt = 0; mt < 2; mt++)
                #pragma unroll
                for (int j = 0; j < 8; j++)
                    mma16816(acc[mt][j][0], acc[mt][j][1], acc[mt][j][2], acc[mt][j][3],
                             af[mt][0], af[mt][1], af[mt][2], af[mt][3],
                             bf[j][0], bf[j][1]);
        }
    }

    const int g  = lane >> 2;
    const int tq = (lane & 3) << 1;
    #pragma unroll
    for (int mt = 0; mt < 2; mt++) {
        int r_lo = row0 + wm * 32 + mt * 16 + g;
        #pragma unroll
        for (int j = 0; j < 8; j++) {
            int c = col0 + wn * 64 + j * 8 + tq;
            float b0 = bias[c], b1 = bias[c + 1];
            float v00 = acc[mt][j][0] + b0, v01 = acc[mt][j][1] + b1;
            float v10 = acc[mt][j][2] + b0, v11 = acc[mt][j][3] + b1;
            if (job) {
                oa[(size_t)r_lo * N + c]           = v00;
                oa[(size_t)r_lo * N + c + 1]       = v01;
                oa[(size_t)(r_lo + 8) * N + c]     = v10;
                oa[(size_t)(r_lo + 8) * N + c + 1] = v11;
            } else {
                valueh[(size_t)r_lo * N + c]           = __float2half(v00);
                valueh[(size_t)r_lo * N + c + 1]       = __float2half(v01);
                valueh[(size_t)(r_lo + 8) * N + c]     = __float2half(v10);
                valueh[(size_t)(r_lo + 8) * N + c + 1] = __float2half(v11);
            }
        }
    }
}

// ---- fused out-projection + residual + LayerNorm: BM=32, BN=256 ------------
#define OB_STRIDE 264
#define XB_STRIDE 264
struct OutSmem {
    __half As[3][32][AS_STRIDE];
    __half Bs[3][GBK][OB_STRIDE];
};
#define OUT_SMEM_BYTES 58368

__global__ __launch_bounds__(256)
void hgemm_out_ln(const __half* __restrict__ A, const __half* __restrict__ B,
                  const float* __restrict__ bias,
                  const float* __restrict__ src,
                  const float* __restrict__ gamma,
                  const float* __restrict__ beta,
                  float* __restrict__ out) {
    extern __shared__ char smem_raw[];
    OutSmem& sm = *(OutSmem*)smem_raw;
    float* xbuf = (float*)smem_raw;

    const int tid  = threadIdx.x;
    const int lane = tid & 31;
    const int warp = tid >> 5;
    const int wm = warp >> 2;
    const int wn = warp & 3;
    const int row0 = blockIdx.x * 32;

    const int a_r = (tid & 127) >> 2;
    const int a_c = (tid & 3) << 3;
    const int b_r = tid >> 5;
    const int b_c = (tid & 31) << 3;

    const __half* Aptr = A + (size_t)row0 * 256;

    auto issue_stage = [&](int s, int k0) {
        if (tid < 128)
            cp16((unsigned)__cvta_generic_to_shared(&sm.As[s][a_r][a_c]),
                 Aptr + (size_t)a_r * 256 + k0 + a_c);
        #pragma unroll
        for (int rr = 0; rr < 4; rr++)
            cp16((unsigned)__cvta_generic_to_shared(&sm.Bs[s][b_r + rr * 8][b_c]),
                 B + (size_t)(k0 + b_r + rr * 8) * 256 + b_c);
    };

    issue_stage(0, 0);   cp_commit();
    issue_stage(1, GBK); cp_commit();

    float acc[8][4] = {};
    const int a_lrow = lane & 15;
    const int a_lcol = (lane >> 4) << 3;

    #pragma unroll 1
    for (int t = 0; t < KITERS; t++) {
        const int sb = t % 3;
        cp_wait<1>();
        __syncthreads();

        if (t + 2 < KITERS) issue_stage((t + 2) % 3, (t + 2) * GBK);
        cp_commit();

        #pragma unroll
        for (int ks = 0; ks < 2; ks++) {
            const int kk = ks * 16;
            unsigned af[4], bf[8][2];
            {
                unsigned addr = (unsigned)__cvta_generic_to_shared(
                    &sm.As[sb][wm * 16 + a_lrow][kk + a_lcol]);
                ldm_x4(af[0], af[1], af[2], af[3], addr);
            }
            #pragma unroll
            for (int nt = 0; nt < 4; nt++) {
                unsigned addr = (unsigned)__cvta_generic_to_shared(
                    &sm.Bs[sb][kk + a_lrow][wn * 64 + nt * 16 + a_lcol]);
                unsigned r0, r1, r2, r3;
                ldm_x4_t(r0, r1, r2, r3, addr);
                bf[nt * 2 + 0][0] = r0; bf[nt * 2 + 0][1] = r1;
                bf[nt * 2 + 1][0] = r2; bf[nt * 2 + 1][1] = r3;
            }
            #pragma unroll
            for (int j = 0; j < 8; j++)
                mma16816(acc[j][0], acc[j][1], acc[j][2], acc[j][3],
                         af[0], af[1], af[2], af[3], bf[j][0], bf[j][1]);
        }
    }

    cp_wait<0>();
    __syncthreads();

    const int g  = lane >> 2;
    const int tq = (lane & 3) << 1;
    {
        int rl = wm * 16 + g;
        #pragma unroll
        for (int j = 0; j < 8; j++) {
            int c = wn * 64 + j * 8 + tq;
            float b0 = bias[c], b1 = bias[c + 1];
            float2 lo = {acc[j][0] + b0, acc[j][1] + b1};
            float2 hi = {acc[j][2] + b0, acc[j][3] + b1};
            *(float2*)&xbuf[rl * XB_STRIDE + c]       = lo;
            *(float2*)&xbuf[(rl + 8) * XB_STRIDE + c] = hi;
        }
    }
    __syncthreads();

    float4 gm0 = *(const float4*)&gamma[lane * 8];
    float4 gm1 = *(const float4*)&gamma[lane * 8 + 4];
    float4 bt0 = *(const float4*)&beta[lane * 8];
    float4 bt1 = *(const float4*)&beta[lane * 8 + 4];

    #pragma unroll 1
    for (int i = 0; i < 4; i++) {
        int rl = warp * 4 + i;
        int rg = row0 + rl;
        float4 x0 = *(float4*)&xbuf[rl * XB_STRIDE + lane * 8];
        float4 x1 = *(float4*)&xbuf[rl * XB_STRIDE + lane * 8 + 4];
        float4 s0 = *(const float4*)&src[(size_t)rg * 256 + lane * 8];
        float4 s1 = *(const float4*)&src[(size_t)rg * 256 + lane * 8 + 4];
        float x[8] = {x0.x + s0.x, x0.y + s0.y, x0.z + s0.z, x0.w + s0.w,
                      x1.x + s1.x, x1.y + s1.y, x1.z + s1.z, x1.w + s1.w};

        float sum = 0.f;
        #pragma unroll
        for (int k = 0; k < 8; k++) sum += x[k];
        #pragma unroll
        for (int o = 16; o > 0; o >>= 1) sum += __shfl_xor_sync(0xffffffffu, sum, o);
        float mean = sum * (1.f / 256.f);

        float v = 0.f;
        #pragma unroll
        for (int k = 0; k < 8; k++) { float d = x[k] - mean; v += d * d; }
        #pragma unroll
        for (int o = 16; o > 0; o >>= 1) v += __shfl_xor_sync(0xffffffffu, v, o);
        float rstd = rsqrtf(v * (1.f / 256.f) + 1e-5f);

        float4 o0 = {(x[0] - mean) * rstd * gm0.x + bt0.x,
                     (x[1] - mean) * rstd * gm0.y + bt0.y,
                     (x[2] - mean) * rstd * gm0.z + bt0.z,
                     (x[3] - mean) * rstd * gm0.w + bt0.w};
        float4 o1 = {(x[4] - mean) * rstd * gm1.x + bt1.x,
                     (x[5] - mean) * rstd * gm1.y + bt1.y,
                     (x[6] - mean) * rstd * gm1.z + bt1.z,
                     (x[7] - mean) * rstd * gm1.w + bt1.w};
        *(float4*)&out[(size_t)rg * 256 + lane * 8]     = o0;
        *(float4*)&out[(size_t)rg * 256 + lane * 8 + 4] = o1;
    }
}

// ---------------- sampler: 4 queries/block, fp32 oa --------------------------
// 512 threads = 4 queries x 4 warps(heads). Per-warp logic identical to R11.
__global__ __launch_bounds__(512)
void sample_kernel(const float* __restrict__ refpts,
                   const float* __restrict__ oa,
                   const __half* __restrict__ value,
                   __half* __restrict__ out) {
    const int tid  = threadIdx.x;
    const int warp = tid >> 5;
    const int lane = tid & 31;
    const int sub  = warp >> 2;            // query within quad (0..3)
    const int h    = warp & 3;
    const int nq   = blockIdx.x * 4 + sub;
    const float* row = oa + (size_t)nq * NOA;

    // ---- phase 1: lane = point pi ----
    float2 off  = ((const float2*)row)[h * 32 + lane];
    float logit = row[HLP2 + h * 32 + lane];

    float m = logit;
    #pragma unroll
    for (int o = 16; o > 0; o >>= 1) m = fmaxf(m, __shfl_xor_sync(0xffffffffu, m, o));
    float e = expf(logit - m);
    float s = e;
    #pragma unroll
    for (int o = 16; o > 0; o >>= 1) s += __shfl_xor_sync(0xffffffffu, s, o);
    float aw = e / s;

    float refv = (lane < 8) ? refpts[(size_t)nq * 8 + lane] : 0.f;
    const int l  = lane >> 3;
    const int Wl = 64 >> l;
    const int lvlS[4] = {0, 4096, 5120, 5376};
    const int base = lvlS[l];
    float rx = __shfl_sync(0xffffffffu, refv, l * 2 + 0);
    float ry = __shfl_sync(0xffffffffu, refv, l * 2 + 1);

    float gx = rx * (float)Wl - 0.5f + off.x;
    float gy = ry * (float)Wl - 0.5f + off.y;
    float x0f = floorf(gx), y0f = floorf(gy);
    int x0 = (int)x0f, y0 = (int)y0f;
    float wx1 = gx - x0f, wy1 = gy - y0f;
    float wx0 = 1.f - wx1, wy0 = 1.f - wy1;

    bool xin0 = (x0 >= 0) & (x0 < Wl);
    bool xin1 = (x0 + 1 >= 0) & (x0 + 1 < Wl);
    bool yin0 = (y0 >= 0) & (y0 < Wl);
    bool yin1 = (y0 + 1 >= 0) & (y0 + 1 < Wl);
    int xc0 = min(max(x0, 0), Wl - 1);
    int xc1 = min(max(x0 + 1, 0), Wl - 1);
    int yc0 = min(max(y0, 0), Wl - 1);
    int yc1 = min(max(y0 + 1, 0), Wl - 1);

    unsigned idxA = (unsigned)(base + yc0 * Wl + xc0)
                  | ((unsigned)(base + yc0 * Wl + xc1) << 16);
    unsigned idxB = (unsigned)(base + yc1 * Wl + xc0)
                  | ((unsigned)(base + yc1 * Wl + xc1) << 16);

    float f00 = (yin0 && xin0) ? aw * wy0 * wx0 : 0.f;
    float f01 = (yin0 && xin1) ? aw * wy0 * wx1 : 0.f;
    float f10 = (yin1 && xin0) ? aw * wy1 * wx0 : 0.f;
    float f11 = (yin1 && xin1) ? aw * wy1 * wx1 : 0.f;
    __half2 hw00 = __float2half2_rn(f00);
    __half2 hw01 = __float2half2_rn(f01);
    __half2 hw10 = __float2half2_rn(f10);
    __half2 hw11 = __float2half2_rn(f11);
    unsigned uw00 = *(unsigned*)&hw00, uw01 = *(unsigned*)&hw01;
    unsigned uw10 = *(unsigned*)&hw10, uw11 = *(unsigned*)&hw11;

    // ---- phase 2 ----
    const int g = lane >> 3;
    const int j = lane & 7;
    const uint4* vgh = (const uint4*)value + (size_t)(nq / LQ) * LIN * 32 + h * 8 + j;

    float acc[8] = {};
    __half2 hacc[4] = {{__float2half(0.f), __float2half(0.f)},
                       {__float2half(0.f), __float2half(0.f)},
                       {__float2half(0.f), __float2half(0.f)},
                       {__float2half(0.f), __float2half(0.f)}};

    #pragma unroll
    for (int pp = 0; pp < 8; pp++) {
        const int pi = pp * 4 + g;
        unsigned pA = __shfl_sync(0xffffffffu, idxA, pi);
        unsigned pB = __shfl_sync(0xffffffffu, idxB, pi);
        unsigned w00 = __shfl_sync(0xffffffffu, uw00, pi);
        unsigned w01 = __shfl_sync(0xffffffffu, uw01, pi);
        unsigned w10 = __shfl_sync(0xffffffffu, uw10, pi);
        unsigned w11 = __shfl_sync(0xffffffffu, uw11, pi);

        uint4 c00 = vgh[(size_t)(pA & 0xFFFFu) * 32];
        uint4 c01 = vgh[(size_t)(pA >> 16) * 32];
        uint4 c10 = vgh[(size_t)(pB & 0xFFFFu) * 32];
        uint4 c11 = vgh[(size_t)(pB >> 16) * 32];

        __half2 hw00v = *(__half2*)&w00, hw01v = *(__half2*)&w01;
        __half2 hw10v = *(__half2*)&w10, hw11v = *(__half2*)&w11;

        const unsigned* u00 = (const unsigned*)&c00;
        const unsigned* u01 = (const unsigned*)&c01;
        const unsigned* u10 = (const unsigned*)&c10;
        const unsigned* u11 = (const unsigned*)&c11;
        #pragma unroll
        for (int k = 0; k < 4; k++) {
            __half2 t = __hmul2(*(const __half2*)&u00[k], hw00v);
            t = __hfma2(*(const __half2*)&u01[k], hw01v, t);
            t = __hfma2(*(const __half2*)&u10[k], hw10v, t);
            t = __hfma2(*(const __half2*)&u11[k], hw11v, t);
            hacc[k] = __hadd2(hacc[k], t);
        }
        if (pp == 3 || pp == 7) {
            #pragma unroll
            for (int k = 0; k < 4; k++) {
                float2 f = __half22float2(hacc[k]);
                acc[2 * k]     += f.x;
                acc[2 * k + 1] += f.y;
                hacc[k] = __half2{__float2half(0.f), __float2half(0.f)};
            }
        }
    }

    #pragma unroll
    for (int i = 0; i < 8; i++) {
        acc[i] += __shfl_xor_sync(0xffffffffu, acc[i], 8);
        acc[i] += __shfl_xor_sync(0xffffffffu, acc[i], 16);
    }

    if (lane < 8) {
        __half2 h0 = __floats2half2_rn(acc[0], acc[1]);
        __half2 h1 = __floats2half2_rn(acc[2], acc[3]);
        __half2 h2 = __floats2half2_rn(acc[4], acc[5]);
        __half2 h3 = __floats2half2_rn(acc[6], acc[7]);
        uint4 o;
        o.x = *(unsigned*)&h0; o.y = *(unsigned*)&h1;
        o.z = *(unsigned*)&h2; o.w = *(unsigned*)&h3;
        ((uint4*)(out + (size_t)nq * CC + h * HD))[lane] = o;
    }
}

// ---------------- launcher --------------------------------------------------
extern "C" void kernel_launch(void* const* d_in, const int* in_sizes, int n_in,
                              void* d_out, int out_size) {
    const float* src_feat   = (const float*)d_in[0];
    const float* refpts     = (const float*)d_in[1];
    const float* key_feat   = (const float*)d_in[2];
    const float* query_pos  = (const float*)d_in[5];
    const float* W_value    = (const float*)d_in[6];
    const float* b_value    = (const float*)d_in[7];
    const float* W_off      = (const float*)d_in[8];
    const float* b_off      = (const float*)d_in[9];
    const float* W_attn     = (const float*)d_in[10];
    const float* b_attn     = (const float*)d_in[11];
    const float* W_out      = (const float*)d_in[12];
    const float* b_out      = (const float*)d_in[13];
    const float* ln_g       = (const float*)d_in[14];
    const float* ln_b       = (const float*)d_in[15];
    float* out = (float*)d_out;

    __half *qh, *keyh, *valueh, *Wvh, *Woah, *Woh, *sampledh;
    float *oa, *boa;
    cudaGetSymbolAddress((void**)&qh,       g_q_h);
    cudaGetSymbolAddress((void**)&keyh,     g_key_h);
    cudaGetSymbolAddress((void**)&valueh,   g_value_h);
    cudaGetSymbolAddress((void**)&oa,       g_oa);
    cudaGetSymbolAddress((void**)&Wvh,      g_Wv_h);
    cudaGetSymbolAddress((void**)&Woah,     g_Woa_h);
    cudaGetSymbolAddress((void**)&Woh,      g_Wo_h);
    cudaGetSymbolAddress((void**)&boa,      g_boa);
    cudaGetSymbolAddress((void**)&sampledh, g_sampled_h);

    cudaFuncSetAttribute(hgemm_out_ln,
                         cudaFuncAttributeMaxDynamicSharedMemorySize,
                         OUT_SMEM_BYTES);

    prep_kernel<<<(2 * N8 + WPREP + 255) / 256, 256>>>(
        src_feat, query_pos, key_feat, W_value, W_off, W_attn, b_off, b_attn,
        W_out, qh, keyh, Wvh, Woah, Woh, boa);

    hgemm_front<<<dim3(NKV / 64, 5), 128>>>(keyh, Wvh, b_value, valueh,
                                            qh, Woah, boa, oa);

    sample_kernel<<<NQ / 4, 512>>>(refpts, oa, valueh, sampledh);

    hgemm_out_ln<<<NQ / 32, 256, OUT_SMEM_BYTES>>>(sampledh, Woh, b_out,
                                                   src_feat, ln_g, ln_b, out);
}

// round 15
// speedup vs baseline: 1.0670x; 1.0448x over previous
#include <cuda_runtime.h>
#include <cuda_fp16.h>
#include <math.h>

// ---------------- problem constants ----------------------------------------
#define NB   2
#define LQ   5440
#define CC   256
#define HH   4
#define LL   4
#define PP   8
#define HD   64
#define LIN  5440
#define NQ   (NB * LQ)   // 10880
#define NKV  (NB * LIN)  // 10880
#define HLP  128
#define HLP2 256
#define NOA  384

// ---------------- scratch ---------------------------------------------------
__device__ __half g_q_h[NQ * CC];
__device__ __half g_key_h[NKV * CC];
__device__ __half g_value_h[NKV * CC];
__device__ float  g_oa[NQ * NOA];
__device__ __half g_Wv_h[CC * CC];
__device__ __half g_Woa_h[CC * NOA];
__device__ __half g_Wo_h[CC * CC];
__device__ float  g_boa[NOA];
__device__ __half g_sampled_h[NQ * CC];

// ---------------- single prep kernel ----------------------------------------
#define N8 (NQ * CC / 8)
#define WPREP (CC * NOA)
__global__ __launch_bounds__(256)
void prep_kernel(const float* __restrict__ src,
                 const float* __restrict__ pos,
                 const float* __restrict__ key,
                 const float* __restrict__ Wv,
                 const float* __restrict__ Woff,
                 const float* __restrict__ Wattn,
                 const float* __restrict__ boff,
                 const float* __restrict__ battn,
                 const float* __restrict__ Wo,
                 __half* __restrict__ qh,
                 __half* __restrict__ keyh,
                 __half* __restrict__ Wvh,
                 __half* __restrict__ Woah,
                 __half* __restrict__ Woh,
                 float* __restrict__ boa) {
    int i = blockIdx.x * blockDim.x + threadIdx.x;
    if (i < N8) {
        float4 s0 = ((const float4*)src)[i * 2];
        float4 s1 = ((const float4*)src)[i * 2 + 1];
        float4 p0 = ((const float4*)pos)[i * 2];
        float4 p1 = ((const float4*)pos)[i * 2 + 1];
        __half2 h0 = __floats2half2_rn(s0.x + p0.x, s0.y + p0.y);
        __half2 h1 = __floats2half2_rn(s0.z + p0.z, s0.w + p0.w);
        __half2 h2 = __floats2half2_rn(s1.x + p1.x, s1.y + p1.y);
        __half2 h3 = __floats2half2_rn(s1.z + p1.z, s1.w + p1.w);
        uint4 o; o.x = *(unsigned*)&h0; o.y = *(unsigned*)&h1;
        o.z = *(unsigned*)&h2; o.w = *(unsigned*)&h3;
        ((uint4*)qh)[i] = o;
    } else if (i < 2 * N8) {
        int j = i - N8;
        float4 k0 = ((const float4*)key)[j * 2];
        float4 k1 = ((const float4*)key)[j * 2 + 1];
        __half2 h0 = __floats2half2_rn(k0.x, k0.y);
        __half2 h1 = __floats2half2_rn(k0.z, k0.w);
        __half2 h2 = __floats2half2_rn(k1.x, k1.y);
        __half2 h3 = __floats2half2_rn(k1.z, k1.w);
        uint4 o; o.x = *(unsigned*)&h0; o.y = *(unsigned*)&h1;
        o.z = *(unsigned*)&h2; o.w = *(unsigned*)&h3;
        ((uint4*)keyh)[j] = o;
    } else {
        int j = i - 2 * N8;
        if (j < WPREP) {
            if (j < CC * CC) {
                Wvh[j] = __float2half(Wv[j]);
                Woh[j] = __float2half(Wo[j]);
            }
            int k = j / NOA, n = j % NOA;
            float w = (n < HLP2) ? Woff[k * HLP2 + n] : Wattn[k * HLP + (n - HLP2)];
            Woah[j] = __float2half(w);
            if (j < NOA) boa[j] = (j < HLP2) ? boff[j] : battn[j - HLP2];
        }
    }
}

// ---------------- GEMM primitives -------------------------------------------
#define GBK 32
#define KITERS 8
#define AS_STRIDE 40

__device__ __forceinline__ void cp16(unsigned dst, const void* src) {
    asm volatile("cp.async.cg.shared.global [%0], [%1], 16;\n" :: "r"(dst), "l"(src));
}
__device__ __forceinline__ void cp_commit() {
    asm volatile("cp.async.commit_group;\n");
}
template <int N>
__device__ __forceinline__ void cp_wait() {
    asm volatile("cp.async.wait_group %0;\n" :: "n"(N));
}
__device__ __forceinline__ void ldm_x4(unsigned& r0, unsigned& r1,
                                       unsigned& r2, unsigned& r3, unsigned addr) {
    asm volatile("ldmatrix.sync.aligned.m8n8.x4.shared.b16 {%0,%1,%2,%3}, [%4];"
                 : "=r"(r0), "=r"(r1), "=r"(r2), "=r"(r3) : "r"(addr));
}
__device__ __forceinline__ void ldm_x4_t(unsigned& r0, unsigned& r1,
                                         unsigned& r2, unsigned& r3, unsigned addr) {
    asm volatile("ldmatrix.sync.aligned.m8n8.x4.trans.shared.b16 {%0,%1,%2,%3}, [%4];"
                 : "=r"(r0), "=r"(r1), "=r"(r2), "=r"(r3) : "r"(addr));
}
__device__ __forceinline__ void mma16816(float& c0, float& c1, float& c2, float& c3,
                                         unsigned a0, unsigned a1, unsigned a2, unsigned a3,
                                         unsigned b0, unsigned b1) {
    asm volatile(
        "mma.sync.aligned.m16n8k16.row.col.f32.f16.f16.f32 "
        "{%0,%1,%2,%3}, {%4,%5,%6,%7}, {%8,%9}, {%0,%1,%2,%3};"
        : "+f"(c0), "+f"(c1), "+f"(c2), "+f"(c3)
        : "r"(a0), "r"(a1), "r"(a2), "r"(a3), "r"(b0), "r"(b1));
}

// ---- front GEMM: BM=64, BN=128, 128 thr (4 warps, warp tile 32x64), 3-stage
#define FB_STRIDE 136
struct FrontSmem {
    __half As[3][64][AS_STRIDE];
    __half Bs[3][GBK][FB_STRIDE];
};

__global__ __launch_bounds__(128, 3)
void hgemm_front(const __half* __restrict__ keyh, const __half* __restrict__ Wvh,
                 const float* __restrict__ bval,  __half* __restrict__ valueh,
                 const __half* __restrict__ qh,   const __half* __restrict__ Woah,
                 const float* __restrict__ boa,   float* __restrict__ oa) {
    __shared__ FrontSmem sm;
    const int tid  = threadIdx.x;
    const int lane = tid & 31;
    const int warp = tid >> 5;
    const int wm = warp >> 1;
    const int wn = warp & 1;

    const int job  = (blockIdx.y < 2) ? 0 : 1;
    const int coly = job ? (blockIdx.y - 2) : blockIdx.y;
    const int N    = job ? NOA : CC;
    const __half* A = job ? qh : keyh;
    const __half* B = job ? Woah : Wvh;
    const float* bias = job ? boa : bval;

    const int row0 = blockIdx.x * 64;
    const int col0 = coly * 128;

    const int a_r = tid >> 2;
    const int a_c = (tid & 3) << 3;
    const int b_r = tid >> 4;
    const int b_c = (tid & 15) << 3;

    const __half* Aptr = A + (size_t)row0 * 256;
    const __half* Bptr = B + col0;

    auto issue_stage = [&](int s, int k0) {
        cp16((unsigned)__cvta_generic_to_shared(&sm.As[s][a_r][a_c]),
             Aptr + (size_t)a_r * 256 + k0 + a_c);
        cp16((unsigned)__cvta_generic_to_shared(&sm.As[s][a_r + 32][a_c]),
             Aptr + (size_t)(a_r + 32) * 256 + k0 + a_c);
        #pragma unroll
        for (int rr = 0; rr < 4; rr++)
            cp16((unsigned)__cvta_generic_to_shared(&sm.Bs[s][b_r + rr * 8][b_c]),
                 Bptr + (size_t)(k0 + b_r + rr * 8) * N + b_c);
    };

    issue_stage(0, 0);   cp_commit();
    issue_stage(1, GBK); cp_commit();

    float acc[2][8][4] = {};
    const int a_lrow = lane & 15;
    const int a_lcol = (lane >> 4) << 3;

    #pragma unroll 1
    for (int t = 0; t < KITERS; t++) {
        const int sb = t % 3;
        cp_wait<1>();
        __syncthreads();

        if (t + 2 < KITERS) issue_stage((t + 2) % 3, (t + 2) * GBK);
        cp_commit();

        #pragma unroll
        for (int ks = 0; ks < 2; ks++) {
            const int kk = ks * 16;
            unsigned af[2][4], bf[8][2];
            #pragma unroll
            for (int mt = 0; mt < 2; mt++) {
                unsigned addr = (unsigned)__cvta_generic_to_shared(
                    &sm.As[sb][wm * 32 + mt * 16 + a_lrow][kk + a_lcol]);
                ldm_x4(af[mt][0], af[mt][1], af[mt][2], af[mt][3], addr);
            }
            #pragma unroll
            for (int nt = 0; nt < 4; nt++) {
                unsigned addr = (unsigned)__cvta_generic_to_shared(
                    &sm.Bs[sb][kk + a_lrow][wn * 64 + nt * 16 + a_lcol]);
                unsigned r0, r1, r2, r3;
                ldm_x4_t(r0, r1, r2, r3, addr);
                bf[nt * 2 + 0][0] = r0; bf[nt * 2 + 0][1] = r1;
                bf[nt * 2 + 1][0] = r2; bf[nt * 2 + 1][1] = r3;
            }
            #pragma unroll
            for (int mt = 0; mt < 2; mt++)
                #pragma unroll
                for (int j = 0; j < 8; j++)
                    mma16816(acc[mt][j][0], acc[mt][j][1], acc[mt][j][2], acc[mt][j][3],
                             af[mt][0], af[mt][1], af[mt][2], af[mt][3],
                             bf[j][0], bf[j][1]);
        }
    }

    const int g  = lane >> 2;
    const int tq = (lane & 3) << 1;
    #pragma unroll
    for (int mt = 0; mt < 2; mt++) {
        int r_lo = row0 + wm * 32 + mt * 16 + g;
        #pragma unroll
        for (int j = 0; j < 8; j++) {
            int c = col0 + wn * 64 + j * 8 + tq;
            float b0 = bias[c], b1 = bias[c + 1];
            float v00 = acc[mt][j][0] + b0, v01 = acc[mt][j][1] + b1;
            float v10 = acc[mt][j][2] + b0, v11 = acc[mt][j][3] + b1;
            if (job) {
                oa[(size_t)r_lo * N + c]           = v00;
                oa[(size_t)r_lo * N + c + 1]       = v01;
                oa[(size_t)(r_lo + 8) * N + c]     = v10;
                oa[(size_t)(r_lo + 8) * N + c + 1] = v11;
            } else {
                valueh[(size_t)r_lo * N + c]           = __float2half(v00);
                valueh[(size_t)r_lo * N + c + 1]       = __float2half(v01);
                valueh[(size_t)(r_lo + 8) * N + c]     = __float2half(v10);
                valueh[(size_t)(r_lo + 8) * N + c + 1] = __float2half(v11);
            }
        }
    }
}

// ---- fused out-projection + residual + LayerNorm: BM=32, BN=256 ------------
#define OB_STRIDE 264
#define XB_STRIDE 264
struct OutSmem {
    __half As[3][32][AS_STRIDE];
    __half Bs[3][GBK][OB_STRIDE];
};
#define OUT_SMEM_BYTES 58368

__global__ __launch_bounds__(256)
void hgemm_out_ln(const __half* __restrict__ A, const __half* __restrict__ B,
                  const float* __restrict__ bias,
                  const float* __restrict__ src,
                  const float* __restrict__ gamma,
                  const float* __restrict__ beta,
                  float* __restrict__ out) {
    extern __shared__ char smem_raw[];
    OutSmem& sm = *(OutSmem*)smem_raw;
    float* xbuf = (float*)smem_raw;

    const int tid  = threadIdx.x;
    const int lane = tid & 31;
    const int warp = tid >> 5;
    const int wm = warp >> 2;
    const int wn = warp & 3;
    const int row0 = blockIdx.x * 32;

    const int a_r = (tid & 127) >> 2;
    const int a_c = (tid & 3) << 3;
    const int b_r = tid >> 5;
    const int b_c = (tid & 31) << 3;

    const __half* Aptr = A + (size_t)row0 * 256;

    auto issue_stage = [&](int s, int k0) {
        if (tid < 128)
            cp16((unsigned)__cvta_generic_to_shared(&sm.As[s][a_r][a_c]),
                 Aptr + (size_t)a_r * 256 + k0 + a_c);
        #pragma unroll
        for (int rr = 0; rr < 4; rr++)
            cp16((unsigned)__cvta_generic_to_shared(&sm.Bs[s][b_r + rr * 8][b_c]),
                 B + (size_t)(k0 + b_r + rr * 8) * 256 + b_c);
    };

    issue_stage(0, 0);   cp_commit();
    issue_stage(1, GBK); cp_commit();

    float acc[8][4] = {};
    const int a_lrow = lane & 15;
    const int a_lcol = (lane >> 4) << 3;

    #pragma unroll 1
    for (int t = 0; t < KITERS; t++) {
        const int sb = t % 3;
        cp_wait<1>();
        __syncthreads();

        if (t + 2 < KITERS) issue_stage((t + 2) % 3, (t + 2) * GBK);
        cp_commit();

        #pragma unroll
        for (int ks = 0; ks < 2; ks++) {
            const int kk = ks * 16;
            unsigned af[4], bf[8][2];
            {
                unsigned addr = (unsigned)__cvta_generic_to_shared(
                    &sm.As[sb][wm * 16 + a_lrow][kk + a_lcol]);
                ldm_x4(af[0], af[1], af[2], af[3], addr);
            }
            #pragma unroll
            for (int nt = 0; nt < 4; nt++) {
                unsigned addr = (unsigned)__cvta_generic_to_shared(
                    &sm.Bs[sb][kk + a_lrow][wn * 64 + nt * 16 + a_lcol]);
                unsigned r0, r1, r2, r3;
                ldm_x4_t(r0, r1, r2, r3, addr);
                bf[nt * 2 + 0][0] = r0; bf[nt * 2 + 0][1] = r1;
                bf[nt * 2 + 1][0] = r2; bf[nt * 2 + 1][1] = r3;
            }
            #pragma unroll
            for (int j = 0; j < 8; j++)
                mma16816(acc[j][0], acc[j][1], acc[j][2], acc[j][3],
                         af[0], af[1], af[2], af[3], bf[j][0], bf[j][1]);
        }
    }

    cp_wait<0>();
    __syncthreads();

    const int g  = lane >> 2;
    const int tq = (lane & 3) << 1;
    {
        int rl = wm * 16 + g;
        #pragma unroll
        for (int j = 0; j < 8; j++) {
            int c = wn * 64 + j * 8 + tq;
            float b0 = bias[c], b1 = bias[c + 1];
            float2 lo = {acc[j][0] + b0, acc[j][1] + b1};
            float2 hi = {acc[j][2] + b0, acc[j][3] + b1};
            *(float2*)&xbuf[rl * XB_STRIDE + c]       = lo;
            *(float2*)&xbuf[(rl + 8) * XB_STRIDE + c] = hi;
        }
    }
    __syncthreads();

    float4 gm0 = *(const float4*)&gamma[lane * 8];
    float4 gm1 = *(const float4*)&gamma[lane * 8 + 4];
    float4 bt0 = *(const float4*)&beta[lane * 8];
    float4 bt1 = *(const float4*)&beta[lane * 8 + 4];

    #pragma unroll 1
    for (int i = 0; i < 4; i++) {
        int rl = warp * 4 + i;
        int rg = row0 + rl;
        float4 x0 = *(float4*)&xbuf[rl * XB_STRIDE + lane * 8];
        float4 x1 = *(float4*)&xbuf[rl * XB_STRIDE + lane * 8 + 4];
        float4 s0 = *(const float4*)&src[(size_t)rg * 256 + lane * 8];
        float4 s1 = *(const float4*)&src[(size_t)rg * 256 + lane * 8 + 4];
        float x[8] = {x0.x + s0.x, x0.y + s0.y, x0.z + s0.z, x0.w + s0.w,
                      x1.x + s1.x, x1.y + s1.y, x1.z + s1.z, x1.w + s1.w};

        float sum = 0.f;
        #pragma unroll
        for (int k = 0; k < 8; k++) sum += x[k];
        #pragma unroll
        for (int o = 16; o > 0; o >>= 1) sum += __shfl_xor_sync(0xffffffffu, sum, o);
        float mean = sum * (1.f / 256.f);

        float v = 0.f;
        #pragma unroll
        for (int k = 0; k < 8; k++) { float d = x[k] - mean; v += d * d; }
        #pragma unroll
        for (int o = 16; o > 0; o >>= 1) v += __shfl_xor_sync(0xffffffffu, v, o);
        float rstd = rsqrtf(v * (1.f / 256.f) + 1e-5f);

        float4 o0 = {(x[0] - mean) * rstd * gm0.x + bt0.x,
                     (x[1] - mean) * rstd * gm0.y + bt0.y,
                     (x[2] - mean) * rstd * gm0.z + bt0.z,
                     (x[3] - mean) * rstd * gm0.w + bt0.w};
        float4 o1 = {(x[4] - mean) * rstd * gm1.x + bt1.x,
                     (x[5] - mean) * rstd * gm1.y + bt1.y,
                     (x[6] - mean) * rstd * gm1.z + bt1.z,
                     (x[7] - mean) * rstd * gm1.w + bt1.w};
        *(float4*)&out[(size_t)rg * 256 + lane * 8]     = o0;
        *(float4*)&out[(size_t)rg * 256 + lane * 8 + 4] = o1;
    }
}

// ---------------- sampler: R11 layout (2 queries/block), __expf --------------
__global__ __launch_bounds__(256)
void sample_kernel(const float* __restrict__ refpts,
                   const float* __restrict__ oa,
                   const __half* __restrict__ value,
                   __half* __restrict__ out) {
    const int tid  = threadIdx.x;
    const int warp = tid >> 5;
    const int lane = tid & 31;
    const int sub  = warp >> 2;
    const int h    = warp & 3;
    const int nq   = blockIdx.x * 2 + sub;
    const float* row = oa + (size_t)nq * NOA;

    // ---- phase 1: lane = point pi ----
    float2 off  = ((const float2*)row)[h * 32 + lane];
    float logit = row[HLP2 + h * 32 + lane];

    float m = logit;
    #pragma unroll
    for (int o = 16; o > 0; o >>= 1) m = fmaxf(m, __shfl_xor_sync(0xffffffffu, m, o));
    float e = __expf(logit - m);
    float s = e;
    #pragma unroll
    for (int o = 16; o > 0; o >>= 1) s += __shfl_xor_sync(0xffffffffu, s, o);
    float aw = e / s;

    float refv = (lane < 8) ? refpts[(size_t)nq * 8 + lane] : 0.f;
    const int l  = lane >> 3;
    const int Wl = 64 >> l;
    const int lvlS[4] = {0, 4096, 5120, 5376};
    const int base = lvlS[l];
    float rx = __shfl_sync(0xffffffffu, refv, l * 2 + 0);
    float ry = __shfl_sync(0xffffffffu, refv, l * 2 + 1);

    float gx = rx * (float)Wl - 0.5f + off.x;
    float gy = ry * (float)Wl - 0.5f + off.y;
    float x0f = floorf(gx), y0f = floorf(gy);
    int x0 = (int)x0f, y0 = (int)y0f;
    float wx1 = gx - x0f, wy1 = gy - y0f;
    float wx0 = 1.f - wx1, wy0 = 1.f - wy1;

    bool xin0 = (x0 >= 0) & (x0 < Wl);
    bool xin1 = (x0 + 1 >= 0) & (x0 + 1 < Wl);
    bool yin0 = (y0 >= 0) & (y0 < Wl);
    bool yin1 = (y0 + 1 >= 0) & (y0 + 1 < Wl);
    int xc0 = min(max(x0, 0), Wl - 1);
    int xc1 = min(max(x0 + 1, 0), Wl - 1);
    int yc0 = min(max(y0, 0), Wl - 1);
    int yc1 = min(max(y0 + 1, 0), Wl - 1);

    unsigned idxA = (unsigned)(base + yc0 * Wl + xc0)
                  | ((unsigned)(base + yc0 * Wl + xc1) << 16);
    unsigned idxB = (unsigned)(base + yc1 * Wl + xc0)
                  | ((unsigned)(base + yc1 * Wl + xc1) << 16);

    float f00 = (yin0 && xin0) ? aw * wy0 * wx0 : 0.f;
    float f01 = (yin0 && xin1) ? aw * wy0 * wx1 : 0.f;
    float f10 = (yin1 && xin0) ? aw * wy1 * wx0 : 0.f;
    float f11 = (yin1 && xin1) ? aw * wy1 * wx1 : 0.f;
    __half2 hw00 = __float2half2_rn(f00);
    __half2 hw01 = __float2half2_rn(f01);
    __half2 hw10 = __float2half2_rn(f10);
    __half2 hw11 = __float2half2_rn(f11);
    unsigned uw00 = *(unsigned*)&hw00, uw01 = *(unsigned*)&hw01;
    unsigned uw10 = *(unsigned*)&hw10, uw11 = *(unsigned*)&hw11;

    // ---- phase 2 ----
    const int g = lane >> 3;
    const int j = lane & 7;
    const uint4* vgh = (const uint4*)value + (size_t)(nq / LQ) * LIN * 32 + h * 8 + j;

    float acc[8] = {};
    __half2 hacc[4] = {{__float2half(0.f), __float2half(0.f)},
                       {__float2half(0.f), __float2half(0.f)},
                       {__float2half(0.f), __float2half(0.f)},
                       {__float2half(0.f), __float2half(0.f)}};

    #pragma unroll
    for (int pp = 0; pp < 8; pp++) {
        const int pi = pp * 4 + g;
        unsigned pA = __shfl_sync(0xffffffffu, idxA, pi);
        unsigned pB = __shfl_sync(0xffffffffu, idxB, pi);
        unsigned w00 = __shfl_sync(0xffffffffu, uw00, pi);
        unsigned w01 = __shfl_sync(0xffffffffu, uw01, pi);
        unsigned w10 = __shfl_sync(0xffffffffu, uw10, pi);
        unsigned w11 = __shfl_sync(0xffffffffu, uw11, pi);

        uint4 c00 = vgh[(size_t)(pA & 0xFFFFu) * 32];
        uint4 c01 = vgh[(size_t)(pA >> 16) * 32];
        uint4 c10 = vgh[(size_t)(pB & 0xFFFFu) * 32];
        uint4 c11 = vgh[(size_t)(pB >> 16) * 32];

        __half2 hw00v = *(__half2*)&w00, hw01v = *(__half2*)&w01;
        __half2 hw10v = *(__half2*)&w10, hw11v = *(__half2*)&w11;

        const unsigned* u00 = (const unsigned*)&c00;
        const unsigned* u01 = (const unsigned*)&c01;
        const unsigned* u10 = (const unsigned*)&c10;
        const unsigned* u11 = (const unsigned*)&c11;
        #pragma unroll
        for (int k = 0; k < 4; k++) {
            __half2 t = __hmul2(*(const __half2*)&u00[k], hw00v);
            t = __hfma2(*(const __half2*)&u01[k], hw01v, t);
            t = __hfma2(*(const __half2*)&u10[k], hw10v, t);
            t = __hfma2(*(const __half2*)&u11[k], hw11v, t);
            hacc[k] = __hadd2(hacc[k], t);
        }
        if (pp == 3 || pp == 7) {
            #pragma unroll
            for (int k = 0; k < 4; k++) {
                float2 f = __half22float2(hacc[k]);
                acc[2 * k]     += f.x;
                acc[2 * k + 1] += f.y;
                hacc[k] = __half2{__float2half(0.f), __float2half(0.f)};
            }
        }
    }

    #pragma unroll
    for (int i = 0; i < 8; i++) {
        acc[i] += __shfl_xor_sync(0xffffffffu, acc[i], 8);
        acc[i] += __shfl_xor_sync(0xffffffffu, acc[i], 16);
    }

    if (lane < 8) {
        __half2 h0 = __floats2half2_rn(acc[0], acc[1]);
        __half2 h1 = __floats2half2_rn(acc[2], acc[3]);
        __half2 h2 = __floats2half2_rn(acc[4], acc[5]);
        __half2 h3 = __floats2half2_rn(acc[6], acc[7]);
        uint4 o;
        o.x = *(unsigned*)&h0; o.y = *(unsigned*)&h1;
        o.z = *(unsigned*)&h2; o.w = *(unsigned*)&h3;
        ((uint4*)(out + (size_t)nq * CC + h * HD))[lane] = o;
    }
}

// ---------------- launcher --------------------------------------------------
extern "C" void kernel_launch(void* const* d_in, const int* in_sizes, int n_in,
                              void* d_out, int out_size) {
    const float* src_feat   = (const float*)d_in[0];
    const float* refpts     = (const float*)d_in[1];
    const float* key_feat   = (const float*)d_in[2];
    const float* query_pos  = (const float*)d_in[5];
    const float* W_value    = (const float*)d_in[6];
    const float* b_value    = (const float*)d_in[7];
    const float* W_off      = (const float*)d_in[8];
    const float* b_off      = (const float*)d_in[9];
    const float* W_attn     = (const float*)d_in[10];
    const float* b_attn     = (const float*)d_in[11];
    const float* W_out      = (const float*)d_in[12];
    const float* b_out      = (const float*)d_in[13];
    const float* ln_g       = (const float*)d_in[14];
    const float* ln_b       = (const float*)d_in[15];
    float* out = (float*)d_out;

    __half *qh, *keyh, *valueh, *Wvh, *Woah, *Woh, *sampledh;
    float *oa, *boa;
    cudaGetSymbolAddress((void**)&qh,       g_q_h);
    cudaGetSymbolAddress((void**)&keyh,     g_key_h);
    cudaGetSymbolAddress((void**)&valueh,   g_value_h);
    cudaGetSymbolAddress((void**)&oa,       g_oa);
    cudaGetSymbolAddress((void**)&Wvh,      g_Wv_h);
    cudaGetSymbolAddress((void**)&Woah,     g_Woa_h);
    cudaGetSymbolAddress((void**)&Woh,      g_Wo_h);
    cudaGetSymbolAddress((void**)&boa,      g_boa);
    cudaGetSymbolAddress((void**)&sampledh, g_sampled_h);

    cudaFuncSetAttribute(hgemm_out_ln,
                         cudaFuncAttributeMaxDynamicSharedMemorySize,
                         OUT_SMEM_BYTES);

    prep_kernel<<<(2 * N8 + WPREP + 255) / 256, 256>>>(
        src_feat, query_pos, key_feat, W_value, W_off, W_attn, b_off, b_attn,
        W_out, qh, keyh, Wvh, Woah, Woh, boa);

    hgemm_front<<<dim3(NKV / 64, 5), 128>>>(keyh, Wvh, b_value, valueh,
                                            qh, Woah, boa, oa);

    sample_kernel<<<NQ / 2, 256>>>(refpts, oa, valueh, sampledh);

    hgemm_out_ln<<<NQ / 32, 256, OUT_SMEM_BYTES>>>(sampledh, Woh, b_out,
                                                   src_feat, ln_g, ln_b, out);
}